// round 8
// baseline (speedup 1.0000x reference)
#include <cuda_runtime.h>
#include <math.h>
#include <stddef.h>

#define N_ENT 2048
#define MENT  64
#define KCAND 32
#define LT 32
#define LB 128
#define LC 128
#define LD 512
#define VOCAB 5053
#define VOCABP 5120
#define EMB 300
#define EMBP 304
#define HDIM 256
#define HH 128
#define CCS 512
#define WIN 5
#define NSEQ 193
#define TT 32
#define G4 512
#define GCAT 1024
#define NFEATP 4224
#define WNC (WIN * CCS)        /* 2560 */
#define WCACHE 96

typedef unsigned long long ull;

/* ------------------------- scratch (device globals) ------------------------ */
__device__ float d_T[(size_t)VOCABP * WNC];
__device__ float d_Bmat[EMBP * WNC];
__device__ float d_embP[VOCABP * EMBP];
__device__ float d_F[NFEATP * CCS];
__device__ float d_WihT[CCS * GCAT];
__device__ float d_preAll[(size_t)NFEATP * GCAT];
__device__ int   d_rowIdx[NSEQ * TT];
__device__ float d_WhhT_f[HH * G4];
__device__ float d_WhhT_b[HH * G4];
__device__ float d_Hcat[NSEQ * TT * HDIM];
__device__ float d_p[2 * MENT * KCAND];
__device__ int   d_used[N_ENT];
__device__ int   d_pos[N_ENT];
__device__ int   d_list[N_ENT];
__device__ int   d_nU[1];

__device__ __forceinline__ float sigm(float x) { return 1.f / (1.f + expf(-x)); }

__device__ __forceinline__ void fma2(ull &d, ull a, ull b) {
    asm("fma.rn.f32x2 %0, %1, %2, %0;" : "+l"(d) : "l"(a), "l"(b));
}
__device__ __forceinline__ ull pack2(float lo, float hi) {
    ull r; asm("mov.b64 %0, {%1, %2};" : "=l"(r) : "f"(lo), "f"(hi)); return r;
}
__device__ __forceinline__ float2 unpack2(ull v) {
    float2 f; asm("mov.b64 {%0, %1}, %2;" : "=f"(f.x), "=f"(f.y) : "l"(v)); return f;
}

/* ------------------------------ prep kernels ------------------------------- */
__global__ void prep0_kernel() {
    int i = blockIdx.x * 256 + threadIdx.x;
    if (i < N_ENT) d_used[i] = 0;
    if (i == N_ENT) d_nU[0] = 0;
}

#define PN1 (CCS * EMB * WIN)
#define PN1B (4 * WNC)
#define PN2 (VOCABP * EMBP)
#define PN3 (2 * G4 * CCS)
#define PN4 (2 * G4 * HH)
#define PN6 (MENT * KCAND)
#define PTOT (PN1 + PN1B + PN2 + PN3 + PN4 + PN6)

__global__ void prep1_kernel(const float* __restrict__ emb,
                             const float* __restrict__ conv_w,
                             const float* __restrict__ Wih_f, const float* __restrict__ Wih_b,
                             const float* __restrict__ Whh_f, const float* __restrict__ Whh_b,
                             const int* __restrict__ cand) {
    int idx = blockIdx.x * 256 + threadIdx.x;
    if (idx < PN1) {
        int c = idx / (EMB * WIN);
        int rem = idx % (EMB * WIN);
        int e = rem / WIN;
        int w = rem % WIN;
        d_Bmat[e * WNC + w * CCS + c] = conv_w[idx];
        return;
    }
    idx -= PN1;
    if (idx < PN1B) { d_Bmat[EMB * WNC + idx] = 0.f; return; }
    idx -= PN1B;
    if (idx < PN2) {
        int r = idx / EMBP, c = idx % EMBP;
        d_embP[idx] = (r < VOCAB && c < EMB) ? emb[r * EMB + c] : 0.f;
        return;
    }
    idx -= PN2;
    if (idx < PN3) {
        int dir = idx / (G4 * CCS);
        int rem = idx % (G4 * CCS);
        int g = rem / CCS, k = rem % CCS;
        d_WihT[k * GCAT + dir * G4 + g] = (dir ? Wih_b : Wih_f)[rem];
        return;
    }
    idx -= PN3;
    if (idx < PN4) {
        int dir = idx / (G4 * HH);
        int rem = idx % (G4 * HH);
        int g = rem / HH, j = rem % HH;
        float* dst = dir ? d_WhhT_b : d_WhhT_f;
        dst[j * G4 + g] = (dir ? Whh_b : Whh_f)[rem];
        return;
    }
    idx -= PN4;
    if (idx < PN6) d_used[cand[idx]] = 1;
}

__global__ void prep2_kernel() {
    int i = blockIdx.x * 256 + threadIdx.x;
    if (i < N_ENT && d_used[i]) {
        int p = atomicAdd(&d_nU[0], 1);
        d_pos[i] = p;
        d_list[p] = i;
    }
}

__global__ void prep3_kernel(const int* __restrict__ cand) {
    int idx = blockIdx.x * 256 + threadIdx.x;
    if (idx >= NSEQ * TT) return;
    int seq = idx / TT, t = idx % TT;
    int r;
    if (seq < 64)       r = d_pos[cand[seq * TT + t]];
    else if (seq < 128) r = 2048 + d_pos[cand[(seq - 64) * TT + t]];
    else if (seq < 192) r = 4096 + (seq - 128);
    else                r = 4160;
    d_rowIdx[idx] = r;
}

/* ----------- fp32x2 GEMM, double-buffered, A stored duplicated ------------- */
/* C[M,N] = A[M,K] @ B[K,N]. 256 thr, 8x8/thr, 2 CTAs/SM.
   rowfilter!=0: skip 128-row blocks fully inside dead zones
   [nU,2048) and [2048+nU,4096).                                              */
__global__ void __launch_bounds__(256, 2) sgemm_k(
        const float* __restrict__ A, const float* __restrict__ B,
        float* __restrict__ C, int N, int K, int nk, int rowfilter) {
    __shared__ __align__(16) float As[2][16][264];   /* duplicated pairs */
    __shared__ __align__(16) float Bs[2][16][132];
    int tid = threadIdx.x;
    int tx = tid & 15, ty = tid >> 4;
    int m0 = blockIdx.y * 128, n0 = blockIdx.x * 128;
    if (rowfilter) {
        int nU = d_nU[0];
        bool act = (m0 < nU) || (m0 + 128 > 2048 && m0 < 2048 + nU) || (m0 + 128 > 4096);
        if (!act) return;
    }
    int aRow = tid >> 1, aK = (tid & 1) * 8;
    int bK = tid >> 4, bN = (tid & 15) * 8;
    const float* Ap = A + (size_t)(m0 + aRow) * K + aK;
    const float* Bp = B + (size_t)bK * N + n0 + bN;

    ull acc[8][4];
#pragma unroll
    for (int i = 0; i < 8; i++)
#pragma unroll
        for (int j = 0; j < 4; j++) acc[i][j] = 0ull;

    float4 ra0 = *(const float4*)(Ap);
    float4 ra1 = *(const float4*)(Ap + 4);
    float4 rb0 = *(const float4*)(Bp);
    float4 rb1 = *(const float4*)(Bp + 4);
    {
        float av[8] = {ra0.x, ra0.y, ra0.z, ra0.w, ra1.x, ra1.y, ra1.z, ra1.w};
#pragma unroll
        for (int q = 0; q < 8; q++)
            *(float2*)&As[0][aK + q][2 * aRow] = make_float2(av[q], av[q]);
    }
    *(float4*)&Bs[0][bK][bN] = rb0;
    *(float4*)&Bs[0][bK][bN + 4] = rb1;
    __syncthreads();

    for (int it = 0; it < nk; it++) {
        int cur = it & 1;
        if (it + 1 < nk) {
            const float* Ap2 = Ap + (it + 1) * 16;
            const float* Bp2 = Bp + (size_t)(it + 1) * 16 * N;
            ra0 = *(const float4*)(Ap2);
            ra1 = *(const float4*)(Ap2 + 4);
            rb0 = *(const float4*)(Bp2);
            rb1 = *(const float4*)(Bp2 + 4);
        }
#pragma unroll
        for (int kk = 0; kk < 16; kk++) {
            const float* arow = &As[cur][kk][ty * 16];
            ulonglong2 aA = *(const ulonglong2*)(arow);
            ulonglong2 aB = *(const ulonglong2*)(arow + 4);
            ulonglong2 aC = *(const ulonglong2*)(arow + 8);
            ulonglong2 aD = *(const ulonglong2*)(arow + 12);
            ull ad[8] = {aA.x, aA.y, aB.x, aB.y, aC.x, aC.y, aD.x, aD.y};
            ulonglong2 bA = *(const ulonglong2*)&Bs[cur][kk][tx * 8];
            ulonglong2 bB = *(const ulonglong2*)&Bs[cur][kk][tx * 8 + 4];
            ull bp[4] = {bA.x, bA.y, bB.x, bB.y};
#pragma unroll
            for (int i = 0; i < 8; i++)
#pragma unroll
                for (int jp = 0; jp < 4; jp++) fma2(acc[i][jp], ad[i], bp[jp]);
        }
        if (it + 1 < nk) {
            int nxt = cur ^ 1;
            float av[8] = {ra0.x, ra0.y, ra0.z, ra0.w, ra1.x, ra1.y, ra1.z, ra1.w};
#pragma unroll
            for (int q = 0; q < 8; q++)
                *(float2*)&As[nxt][aK + q][2 * aRow] = make_float2(av[q], av[q]);
            *(float4*)&Bs[nxt][bK][bN] = rb0;
            *(float4*)&Bs[nxt][bK][bN + 4] = rb1;
            __syncthreads();
        }
    }
#pragma unroll
    for (int i = 0; i < 8; i++) {
        int m = m0 + ty * 8 + i;
#pragma unroll
        for (int jp = 0; jp < 4; jp++) {
            float2 f = unpack2(acc[i][jp]);
            *(float2*)&C[(size_t)m * N + n0 + tx * 8 + 2 * jp] = f;
        }
    }
}

/* -------------------- conv via token table + maxpool ----------------------- */
/* Compact entity rows: title -> d_F[i], body -> d_F[2048+i], i = compact pos.
   Blocks for unused entity slots exit immediately.                           */
__global__ void __launch_bounds__(256) conv_all(
        const int* __restrict__ title, const int* __restrict__ body,
        const int* __restrict__ ctx, const int* __restrict__ doc,
        const float* __restrict__ bias) {
    int blk = blockIdx.x;
    const int* toks; int L; int row;
    if (blk == 0) { toks = doc; L = LD; row = 4160; }
    else if (blk <= 2048) {
        int i = blk - 1;
        if (i >= d_nU[0]) return;
        toks = body + (size_t)d_list[i] * LB; L = LB; row = 2048 + i;
    } else if (blk <= 2112) {
        int i = blk - 2049;
        toks = ctx + (size_t)i * LC; L = LC; row = 4096 + i;
    } else {
        int i = blk - 2113;
        if (i >= d_nU[0]) return;
        toks = title + (size_t)d_list[i] * LT; L = LT; row = i;
    }
    int c2 = threadIdx.x;
    __shared__ int st[LD];
    for (int i = c2; i < L; i += 256) st[i] = toks[i];
    __syncthreads();
    float2 b = *(const float2*)&bias[2 * c2];
    float2 m = make_float2(0.f, 0.f);
    int P = L - WIN + 1;
    for (int p = 0; p < P; p++) {
        float2 acc = b;
#pragma unroll
        for (int w = 0; w < WIN; w++) {
            int v = st[p + w];
            float2 tv = *(const float2*)&d_T[((size_t)v * WIN + w) * CCS + 2 * c2];
            acc.x += tv.x; acc.y += tv.y;
        }
        m.x = fmaxf(m.x, acc.x);
        m.y = fmaxf(m.y, acc.y);
    }
    *(float2*)&d_F[(size_t)row * CCS + 2 * c2] = m;
}

/* ----------------------------- LSTM recurrence ----------------------------- */
__global__ void __launch_bounds__(512) lstm_kernel(
        const float* __restrict__ bih_f, const float* __restrict__ bhh_f,
        const float* __restrict__ bih_b, const float* __restrict__ bhh_b) {
    extern __shared__ float sW[];
    int dir = blockIdx.y;
    int s0 = blockIdx.x * 4;
    const float* WT = dir ? d_WhhT_b : d_WhhT_f;
    int g = threadIdx.x;
    float bias = dir ? (bih_b[g] + bhh_b[g]) : (bih_f[g] + bhh_f[g]);
    __shared__ float shT[HH][4];
    __shared__ float sg[4][G4];
    __shared__ int ridx[4][TT];
    int so = g >> 7, d = g & 127;
    float creg = 0.f;
    shT[d][so] = 0.f;
    for (int i = g; i < WCACHE * G4; i += 512) sW[i] = WT[i];
    for (int i = g; i < 4 * TT; i += 512) {
        int s = i >> 5, t = i & 31;
        int seq = s0 + s; if (seq >= NSEQ) seq = NSEQ - 1;
        ridx[s][t] = d_rowIdx[seq * TT + t];
    }
    __syncthreads();
    int nv = NSEQ - s0; if (nv > 4) nv = 4;
    const float* preBase = d_preAll + dir * G4 + g;
    for (int step = 0; step < TT; step++) {
        int t = dir ? (TT - 1 - step) : step;
        float p0 = preBase[(size_t)ridx[0][t] * GCAT] + bias;
        float p1 = preBase[(size_t)ridx[1][t] * GCAT] + bias;
        float p2 = preBase[(size_t)ridx[2][t] * GCAT] + bias;
        float p3 = preBase[(size_t)ridx[3][t] * GCAT] + bias;
        ull a01 = pack2(p0, p1);
        ull a23 = pack2(p2, p3);
#pragma unroll 8
        for (int j = 0; j < WCACHE; j++) {
            float wv = sW[j * G4 + g];
            ulonglong2 h2 = *(const ulonglong2*)&shT[j][0];
            ull wd = pack2(wv, wv);
            fma2(a01, wd, h2.x);
            fma2(a23, wd, h2.y);
        }
#pragma unroll 8
        for (int j = WCACHE; j < HH; j++) {
            float wv = __ldg(WT + (size_t)j * G4 + g);
            ulonglong2 h2 = *(const ulonglong2*)&shT[j][0];
            ull wd = pack2(wv, wv);
            fma2(a01, wd, h2.x);
            fma2(a23, wd, h2.y);
        }
        float2 f01 = unpack2(a01);
        float2 f23 = unpack2(a23);
        sg[0][g] = f01.x; sg[1][g] = f01.y; sg[2][g] = f23.x; sg[3][g] = f23.y;
        __syncthreads();
        if (so < nv) {
            float iv = sg[so][d];
            float fv = sg[so][d + HH];
            float gv = sg[so][d + 2 * HH];
            float ov = sg[so][d + 3 * HH];
            float cn = sigm(fv) * creg + sigm(iv) * tanhf(gv);
            float hn = sigm(ov) * tanhf(cn);
            creg = cn;
            shT[d][so] = hn;
            d_Hcat[((size_t)(s0 + so) * TT + t) * HDIM + dir * HH + d] = hn;
        }
        __syncthreads();
    }
}

/* ------------------------------ BiDAF + score ------------------------------ */
__global__ void att_kernel(const float* __restrict__ wc, const float* __restrict__ bc,
                           const float* __restrict__ wq, const float* __restrict__ bq,
                           const float* __restrict__ wcq, const float* __restrict__ bcq,
                           const float* __restrict__ wz, const float* __restrict__ bz) {
    int b = blockIdx.x;
    int pair = blockIdx.y;
    int tid = threadIdx.x;
    int cseq = pair ? 192 : 128 + b;
    int qseq = pair ? 64 + b : b;
    const float* Cg = d_Hcat + (size_t)cseq * TT * HDIM;
    const float* Qg = d_Hcat + (size_t)qseq * TT * HDIM;
    __shared__ float CS[TT * HDIM];
    __shared__ float S[TT * TT];
    __shared__ float Aw[TT * TT];
    __shared__ float CD[TT], QD[TT], SMX[TT], BV[TT];
    __shared__ float Q2C[HDIM];
    __shared__ float RED[8];
    for (int i = tid; i < TT * HDIM; i += 256) CS[i] = Cg[i];
    __syncthreads();
    if (tid < TT) {
        float s = 0.f;
        const float* crow = CS + tid * HDIM;
        for (int d = 0; d < HDIM; d++) s += crow[d] * wc[d];
        CD[tid] = s;
    } else if (tid < 2 * TT) {
        int j = tid - TT;
        float s = 0.f;
        const float* qrow = Qg + (size_t)j * HDIM;
        for (int d = 0; d < HDIM; d++) s += qrow[d] * wq[d];
        QD[j] = s;
    }
    __syncthreads();
    float bsum = bc[0] + bq[0] + bcq[0];
#pragma unroll
    for (int r = 0; r < 4; r++) {
        int pi = tid * 4 + r;
        int i = pi >> 5, j = pi & 31;
        const float* crow = CS + i * HDIM;
        const float* qrow = Qg + (size_t)j * HDIM;
        float s = 0.f;
        for (int d = 0; d < HDIM; d++) s += crow[d] * qrow[d] * wcq[d];
        S[pi] = s + CD[i] + QD[j] + bsum;
    }
    __syncthreads();
    int lane = tid & 31, warp = tid >> 5;
    for (int i = warp; i < TT; i += 8) {
        float v = S[i * 32 + lane];
        float mx = v;
        for (int o = 16; o; o >>= 1) mx = fmaxf(mx, __shfl_xor_sync(0xffffffffu, mx, o));
        float e = expf(v - mx);
        float sm = e;
        for (int o = 16; o; o >>= 1) sm += __shfl_xor_sync(0xffffffffu, sm, o);
        Aw[i * 32 + lane] = e / sm;
        if (lane == 0) SMX[i] = mx;
    }
    __syncthreads();
    if (warp == 0) {
        float v = SMX[lane];
        float mx = v;
        for (int o = 16; o; o >>= 1) mx = fmaxf(mx, __shfl_xor_sync(0xffffffffu, mx, o));
        float e = expf(v - mx);
        float sm = e;
        for (int o = 16; o; o >>= 1) sm += __shfl_xor_sync(0xffffffffu, sm, o);
        BV[lane] = e / sm;
    }
    __syncthreads();
    {
        float s = 0.f;
        for (int i = 0; i < TT; i++) s += BV[i] * CS[i * HDIM + tid];
        Q2C[tid] = s;
    }
    __syncthreads();
    float bzv = bz[0];
    for (int i = 0; i < TT; i++) {
        int d = tid;
        float c2q = 0.f;
        for (int j = 0; j < TT; j++) c2q += Aw[i * 32 + j] * Qg[(size_t)j * HDIM + d];
        float cv = CS[i * HDIM + d];
        float term = cv * wz[d] + c2q * wz[HDIM + d] + cv * c2q * wz[2 * HDIM + d]
                   + cv * Q2C[d] * wz[3 * HDIM + d];
        for (int o = 16; o; o >>= 1) term += __shfl_xor_sync(0xffffffffu, term, o);
        if (lane == 0) RED[warp] = term;
        __syncthreads();
        if (tid == 0) {
            float tot = 0.f;
            for (int w2 = 0; w2 < 8; w2++) tot += RED[w2];
            d_p[(pair * MENT + b) * KCAND + i] = tot + bzv;
        }
        __syncthreads();
    }
}

__global__ void zero_kernel(float* __restrict__ out, int n) {
    int idx = blockIdx.x * blockDim.x + threadIdx.x;
    if (idx < n) out[idx] = 0.f;
}

__global__ void score_kernel(const int* __restrict__ cand,
                             const float* __restrict__ wp1, const float* __restrict__ bp1,
                             const float* __restrict__ wp2, const float* __restrict__ bp2,
                             float* __restrict__ out) {
    int b = blockIdx.x, i = threadIdx.x;
    float p1 = d_p[(0 * MENT + b) * KCAND + i];
    float p2 = d_p[(1 * MENT + b) * KCAND + i];
    float sc = wp1[0] * p1 + bp1[0] + wp2[0] * p2 + bp2[0];
    float mx = sc;
    for (int o = 16; o; o >>= 1) mx = fmaxf(mx, __shfl_xor_sync(0xffffffffu, mx, o));
    float e = expf(sc - mx);
    float es = e;
    for (int o = 16; o; o >>= 1) es += __shfl_xor_sync(0xffffffffu, es, o);
    float ssum = sc;
    for (int o = 16; o; o >>= 1) ssum += __shfl_xor_sync(0xffffffffu, ssum, o);
    int col = cand[b * KCAND + i];
    out[(size_t)b * N_ENT + col] = sc;
    out[(size_t)MENT * N_ENT + (size_t)b * N_ENT + col] = e / es;
    out[(size_t)2 * MENT * N_ENT + (size_t)b * N_ENT + col] = sc / ssum;
}

/* ------------------------------- launcher ---------------------------------- */
extern "C" void kernel_launch(void* const* d_in, const int* in_sizes, int n_in,
                              void* d_out, int out_size) {
    const int*   title  = (const int*)d_in[0];
    const int*   body   = (const int*)d_in[1];
    const int*   ctx    = (const int*)d_in[3];
    const int*   doc    = (const int*)d_in[4];
    const int*   cand   = (const int*)d_in[5];
    const float* emb    = (const float*)d_in[6];
    const float* conv_w = (const float*)d_in[7];
    const float* conv_b = (const float*)d_in[8];
    const float* Wih_f  = (const float*)d_in[9];
    const float* Whh_f  = (const float*)d_in[10];
    const float* bih_f  = (const float*)d_in[11];
    const float* bhh_f  = (const float*)d_in[12];
    const float* Wih_b  = (const float*)d_in[13];
    const float* Whh_b  = (const float*)d_in[14];
    const float* bih_b  = (const float*)d_in[15];
    const float* bhh_b  = (const float*)d_in[16];
    const float* wc  = (const float*)d_in[17];
    const float* bc  = (const float*)d_in[18];
    const float* wq  = (const float*)d_in[19];
    const float* bq  = (const float*)d_in[20];
    const float* wcq = (const float*)d_in[21];
    const float* bcq = (const float*)d_in[22];
    const float* wz  = (const float*)d_in[23];
    const float* bz  = (const float*)d_in[24];
    const float* wp1 = (const float*)d_in[25];
    const float* bp1 = (const float*)d_in[26];
    const float* wp2 = (const float*)d_in[27];
    const float* bp2 = (const float*)d_in[28];
    float* out = (float*)d_out;
    (void)in_sizes; (void)n_in; (void)out_size;

    float *pT, *pB, *pE, *pF, *pWT, *pPre;
    cudaGetSymbolAddress((void**)&pT, d_T);
    cudaGetSymbolAddress((void**)&pB, d_Bmat);
    cudaGetSymbolAddress((void**)&pE, d_embP);
    cudaGetSymbolAddress((void**)&pF, d_F);
    cudaGetSymbolAddress((void**)&pWT, d_WihT);
    cudaGetSymbolAddress((void**)&pPre, d_preAll);

    static int smem_set = 0;
    if (!smem_set) {
        cudaFuncSetAttribute(lstm_kernel, cudaFuncAttributeMaxDynamicSharedMemorySize,
                             WCACHE * G4 * (int)sizeof(float));
        smem_set = 1;
    }

    /* 1: reset used flags + counter */
    prep0_kernel<<<(N_ENT + 256) / 256, 256>>>();

    /* 2: transposes / padded fills / used-entity scatter */
    prep1_kernel<<<(PTOT + 255) / 256, 256>>>(emb, conv_w, Wih_f, Wih_b, Whh_f, Whh_b, cand);

    /* 3: compact entity list + positions */
    prep2_kernel<<<(N_ENT + 255) / 256, 256>>>();

    /* 4: LSTM row index table (compact rows) */
    prep3_kernel<<<(NSEQ * TT + 255) / 256, 256>>>(cand);

    /* 5: zero output */
    {
        int n = 3 * MENT * N_ENT;
        zero_kernel<<<(n + 255) / 256, 256>>>(out, n);
    }

    /* 6: token table T = embP @ BmatP : [5120 x 2560], K=304 */
    sgemm_k<<<dim3(WNC / 128, VOCABP / 128), 256>>>(pE, pB, pT, WNC, EMBP, EMBP / 16, 0);

    /* 7: char-CNN features (used entities only) */
    conv_all<<<1 + N_ENT + MENT + N_ENT, 256>>>(title, body, ctx, doc, conv_b);

    /* 8: pre-activations: [4224 x 1024], K=512, dead row-blocks skipped */
    sgemm_k<<<dim3(GCAT / 128, NFEATP / 128), 256>>>(pF, pWT, pPre, GCAT, CCS, CCS / 16, 1);

    /* 9: recurrence */
    lstm_kernel<<<dim3((NSEQ + 3) / 4, 2), 512, WCACHE * G4 * sizeof(float)>>>(
        bih_f, bhh_f, bih_b, bhh_b);

    /* 10: BiDAF attention + projection */
    att_kernel<<<dim3(MENT, 2), 256>>>(wc, bc, wq, bq, wcq, bcq, wz, bz);

    /* 11: score, softmax, sum-normalize, scatter */
    score_kernel<<<MENT, KCAND>>>(cand, wp1, bp1, wp2, bp2, out);
}

// round 10
// speedup vs baseline: 1.0674x; 1.0674x over previous
#include <cuda_runtime.h>
#include <math.h>
#include <stddef.h>

#define N_ENT 2048
#define MENT  64
#define KCAND 32
#define LT 32
#define LB 128
#define LC 128
#define LD 512
#define VOCAB 5053
#define VOCABP 5120
#define EMB 300
#define EMBP 304
#define HDIM 256
#define HH 128
#define CCS 512
#define WIN 5
#define NSEQ 193
#define TT 32
#define G4 512
#define GCAT 1024
#define NFEATP 4224
#define WNC (WIN * CCS)        /* 2560 */
#define WCACHE 96

typedef unsigned long long ull;

/* ------------------------- scratch (device globals) ------------------------ */
__device__ float d_T[(size_t)VOCABP * WNC];
__device__ float d_Bmat[EMBP * WNC];
__device__ float d_embP[VOCABP * EMBP];
__device__ float d_F[NFEATP * CCS];
__device__ float d_WihT[CCS * GCAT];
__device__ float d_preAll[(size_t)NFEATP * GCAT];
__device__ int   d_rowIdx[NSEQ * TT];
__device__ float d_WhhT_f[HH * G4];
__device__ float d_WhhT_b[HH * G4];
__device__ float d_Hcat[NSEQ * TT * HDIM];
__device__ float d_p[2 * MENT * KCAND];
__device__ int   d_used[N_ENT];
__device__ int   d_pos[N_ENT];
__device__ int   d_list[N_ENT];
__device__ int   d_nU[1];

__device__ __forceinline__ float sigm(float x) { return 1.f / (1.f + expf(-x)); }

__device__ __forceinline__ void fma2(ull &d, ull a, ull b) {
    asm("fma.rn.f32x2 %0, %1, %2, %0;" : "+l"(d) : "l"(a), "l"(b));
}
__device__ __forceinline__ ull pack2(float lo, float hi) {
    ull r; asm("mov.b64 %0, {%1, %2};" : "=l"(r) : "f"(lo), "f"(hi)); return r;
}
__device__ __forceinline__ float2 unpack2(ull v) {
    float2 f; asm("mov.b64 {%0, %1}, %2;" : "=f"(f.x), "=f"(f.y) : "l"(v)); return f;
}

/* ------------------------------ prep kernels ------------------------------- */
__global__ void prep0_kernel() {
    int i = blockIdx.x * 256 + threadIdx.x;
    if (i < N_ENT) d_used[i] = 0;
    if (i == N_ENT) d_nU[0] = 0;
}

#define PN1 (CCS * EMB * WIN)
#define PN1B (4 * WNC)
#define PN2 (VOCABP * EMBP)
#define PN3 (2 * G4 * CCS)
#define PN4 (2 * G4 * HH)
#define PN6 (MENT * KCAND)
#define PTOT (PN1 + PN1B + PN2 + PN3 + PN4 + PN6)

__global__ void prep1_kernel(const float* __restrict__ emb,
                             const float* __restrict__ conv_w,
                             const float* __restrict__ Wih_f, const float* __restrict__ Wih_b,
                             const float* __restrict__ Whh_f, const float* __restrict__ Whh_b,
                             const int* __restrict__ cand) {
    int idx = blockIdx.x * 256 + threadIdx.x;
    if (idx < PN1) {
        int c = idx / (EMB * WIN);
        int rem = idx % (EMB * WIN);
        int e = rem / WIN;
        int w = rem % WIN;
        d_Bmat[e * WNC + w * CCS + c] = conv_w[idx];
        return;
    }
    idx -= PN1;
    if (idx < PN1B) { d_Bmat[EMB * WNC + idx] = 0.f; return; }
    idx -= PN1B;
    if (idx < PN2) {
        int r = idx / EMBP, c = idx % EMBP;
        d_embP[idx] = (r < VOCAB && c < EMB) ? emb[r * EMB + c] : 0.f;
        return;
    }
    idx -= PN2;
    if (idx < PN3) {
        int dir = idx / (G4 * CCS);
        int rem = idx % (G4 * CCS);
        int g = rem / CCS, k = rem % CCS;
        d_WihT[k * GCAT + dir * G4 + g] = (dir ? Wih_b : Wih_f)[rem];
        return;
    }
    idx -= PN3;
    if (idx < PN4) {
        int dir = idx / (G4 * HH);
        int rem = idx % (G4 * HH);
        int g = rem / HH, j = rem % HH;
        float* dst = dir ? d_WhhT_b : d_WhhT_f;
        dst[j * G4 + g] = (dir ? Whh_b : Whh_f)[rem];
        return;
    }
    idx -= PN4;
    if (idx < PN6) d_used[cand[idx]] = 1;
}

__global__ void prep2_kernel() {
    int i = blockIdx.x * 256 + threadIdx.x;
    if (i < N_ENT && d_used[i]) {
        int p = atomicAdd(&d_nU[0], 1);
        d_pos[i] = p;
        d_list[p] = i;
    }
}

__global__ void prep3_kernel(const int* __restrict__ cand) {
    int idx = blockIdx.x * 256 + threadIdx.x;
    if (idx >= NSEQ * TT) return;
    int seq = idx / TT, t = idx % TT;
    int r;
    if (seq < 64)       r = d_pos[cand[seq * TT + t]];
    else if (seq < 128) r = 2048 + d_pos[cand[(seq - 64) * TT + t]];
    else if (seq < 192) r = 4096 + (seq - 128);
    else                r = 4160;
    d_rowIdx[idx] = r;
}

/* ----------- fp32x2 GEMM (FFMA2), double-buffered, no guards --------------- */
/* C[M,N] = A[M,K] @ B[K,N]. M,N multiples of 128; K multiple of 16.
   256 threads, 8x8/thread, 2 CTAs/SM. A lanes duplicated in REGISTERS
   (pack2), keeping smem traffic at the FMA floor (64B/thread/kk).
   rowfilter!=0: skip 128-row blocks fully inside dead zones
   [nU,2048) and [2048+nU,4096).                                              */
__global__ void __launch_bounds__(256, 2) sgemm_k(
        const float* __restrict__ A, const float* __restrict__ B,
        float* __restrict__ C, int N, int K, int nk, int rowfilter) {
    __shared__ float As[2][16][132];
    __shared__ float Bs[2][16][132];
    int tid = threadIdx.x;
    int tx = tid & 15, ty = tid >> 4;
    int m0 = blockIdx.y * 128, n0 = blockIdx.x * 128;
    if (rowfilter) {
        int nU = d_nU[0];
        bool act = (m0 < nU) || (m0 + 128 > 2048 && m0 < 2048 + nU) || (m0 + 128 > 4096);
        if (!act) return;
    }
    int aRow = tid >> 1, aK = (tid & 1) * 8;
    int bK = tid >> 4, bN = (tid & 15) * 8;
    const float* Ap = A + (size_t)(m0 + aRow) * K + aK;
    const float* Bp = B + (size_t)bK * N + n0 + bN;

    ull acc[8][4];
#pragma unroll
    for (int i = 0; i < 8; i++)
#pragma unroll
        for (int j = 0; j < 4; j++) acc[i][j] = 0ull;

    float4 ra0 = *(const float4*)(Ap);
    float4 ra1 = *(const float4*)(Ap + 4);
    float4 rb0 = *(const float4*)(Bp);
    float4 rb1 = *(const float4*)(Bp + 4);
    As[0][aK + 0][aRow] = ra0.x; As[0][aK + 1][aRow] = ra0.y;
    As[0][aK + 2][aRow] = ra0.z; As[0][aK + 3][aRow] = ra0.w;
    As[0][aK + 4][aRow] = ra1.x; As[0][aK + 5][aRow] = ra1.y;
    As[0][aK + 6][aRow] = ra1.z; As[0][aK + 7][aRow] = ra1.w;
    *(float4*)&Bs[0][bK][bN] = rb0;
    *(float4*)&Bs[0][bK][bN + 4] = rb1;
    __syncthreads();

    for (int it = 0; it < nk; it++) {
        int cur = it & 1;
        if (it + 1 < nk) {
            const float* Ap2 = Ap + (it + 1) * 16;
            const float* Bp2 = Bp + (size_t)(it + 1) * 16 * N;
            ra0 = *(const float4*)(Ap2);
            ra1 = *(const float4*)(Ap2 + 4);
            rb0 = *(const float4*)(Bp2);
            rb1 = *(const float4*)(Bp2 + 4);
        }
#pragma unroll
        for (int kk = 0; kk < 16; kk++) {
            float4 a0 = *(const float4*)&As[cur][kk][ty * 8];
            float4 a1 = *(const float4*)&As[cur][kk][ty * 8 + 4];
            ulonglong2 bA = *(const ulonglong2*)&Bs[cur][kk][tx * 8];
            ulonglong2 bB = *(const ulonglong2*)&Bs[cur][kk][tx * 8 + 4];
            ull bp[4] = {bA.x, bA.y, bB.x, bB.y};
            float rav[8] = {a0.x, a0.y, a0.z, a0.w, a1.x, a1.y, a1.z, a1.w};
            ull ad[8];
#pragma unroll
            for (int i = 0; i < 8; i++) ad[i] = pack2(rav[i], rav[i]);
#pragma unroll
            for (int i = 0; i < 8; i++)
#pragma unroll
                for (int jp = 0; jp < 4; jp++) fma2(acc[i][jp], ad[i], bp[jp]);
        }
        if (it + 1 < nk) {
            int nxt = cur ^ 1;
            As[nxt][aK + 0][aRow] = ra0.x; As[nxt][aK + 1][aRow] = ra0.y;
            As[nxt][aK + 2][aRow] = ra0.z; As[nxt][aK + 3][aRow] = ra0.w;
            As[nxt][aK + 4][aRow] = ra1.x; As[nxt][aK + 5][aRow] = ra1.y;
            As[nxt][aK + 6][aRow] = ra1.z; As[nxt][aK + 7][aRow] = ra1.w;
            *(float4*)&Bs[nxt][bK][bN] = rb0;
            *(float4*)&Bs[nxt][bK][bN + 4] = rb1;
            __syncthreads();
        }
    }
#pragma unroll
    for (int i = 0; i < 8; i++) {
        int m = m0 + ty * 8 + i;
#pragma unroll
        for (int jp = 0; jp < 4; jp++) {
            float2 f = unpack2(acc[i][jp]);
            *(float2*)&C[(size_t)m * N + n0 + tx * 8 + 2 * jp] = f;
        }
    }
}

/* -------------------- conv via token table + maxpool ----------------------- */
/* Compact entity rows: title -> d_F[i], body -> d_F[2048+i], i = compact pos.
   Blocks for unused entity slots exit immediately.                           */
__global__ void __launch_bounds__(256) conv_all(
        const int* __restrict__ title, const int* __restrict__ body,
        const int* __restrict__ ctx, const int* __restrict__ doc,
        const float* __restrict__ bias) {
    int blk = blockIdx.x;
    const int* toks; int L; int row;
    if (blk == 0) { toks = doc; L = LD; row = 4160; }
    else if (blk <= 2048) {
        int i = blk - 1;
        if (i >= d_nU[0]) return;
        toks = body + (size_t)d_list[i] * LB; L = LB; row = 2048 + i;
    } else if (blk <= 2112) {
        int i = blk - 2049;
        toks = ctx + (size_t)i * LC; L = LC; row = 4096 + i;
    } else {
        int i = blk - 2113;
        if (i >= d_nU[0]) return;
        toks = title + (size_t)d_list[i] * LT; L = LT; row = i;
    }
    int c2 = threadIdx.x;
    __shared__ int st[LD];
    for (int i = c2; i < L; i += 256) st[i] = toks[i];
    __syncthreads();
    float2 b = *(const float2*)&bias[2 * c2];
    float2 m = make_float2(0.f, 0.f);
    int P = L - WIN + 1;
    for (int p = 0; p < P; p++) {
        float2 acc = b;
#pragma unroll
        for (int w = 0; w < WIN; w++) {
            int v = st[p + w];
            float2 tv = *(const float2*)&d_T[((size_t)v * WIN + w) * CCS + 2 * c2];
            acc.x += tv.x; acc.y += tv.y;
        }
        m.x = fmaxf(m.x, acc.x);
        m.y = fmaxf(m.y, acc.y);
    }
    *(float2*)&d_F[(size_t)row * CCS + 2 * c2] = m;
}

/* ----------------------------- LSTM recurrence ----------------------------- */
__global__ void __launch_bounds__(512) lstm_kernel(
        const float* __restrict__ bih_f, const float* __restrict__ bhh_f,
        const float* __restrict__ bih_b, const float* __restrict__ bhh_b) {
    extern __shared__ float sW[];
    int dir = blockIdx.y;
    int s0 = blockIdx.x * 4;
    const float* WT = dir ? d_WhhT_b : d_WhhT_f;
    int g = threadIdx.x;
    float bias = dir ? (bih_b[g] + bhh_b[g]) : (bih_f[g] + bhh_f[g]);
    __shared__ float shT[HH][4];
    __shared__ float sg[4][G4];
    __shared__ int ridx[4][TT];
    int so = g >> 7, d = g & 127;
    float creg = 0.f;
    shT[d][so] = 0.f;
    for (int i = g; i < WCACHE * G4; i += 512) sW[i] = WT[i];
    for (int i = g; i < 4 * TT; i += 512) {
        int s = i >> 5, t = i & 31;
        int seq = s0 + s; if (seq >= NSEQ) seq = NSEQ - 1;
        ridx[s][t] = d_rowIdx[seq * TT + t];
    }
    __syncthreads();
    int nv = NSEQ - s0; if (nv > 4) nv = 4;
    const float* preBase = d_preAll + dir * G4 + g;
    for (int step = 0; step < TT; step++) {
        int t = dir ? (TT - 1 - step) : step;
        float p0 = preBase[(size_t)ridx[0][t] * GCAT] + bias;
        float p1 = preBase[(size_t)ridx[1][t] * GCAT] + bias;
        float p2 = preBase[(size_t)ridx[2][t] * GCAT] + bias;
        float p3 = preBase[(size_t)ridx[3][t] * GCAT] + bias;
        ull a01 = pack2(p0, p1);
        ull a23 = pack2(p2, p3);
#pragma unroll 8
        for (int j = 0; j < WCACHE; j++) {
            float wv = sW[j * G4 + g];
            ulonglong2 h2 = *(const ulonglong2*)&shT[j][0];
            ull wd = pack2(wv, wv);
            fma2(a01, wd, h2.x);
            fma2(a23, wd, h2.y);
        }
#pragma unroll 8
        for (int j = WCACHE; j < HH; j++) {
            float wv = __ldg(WT + (size_t)j * G4 + g);
            ulonglong2 h2 = *(const ulonglong2*)&shT[j][0];
            ull wd = pack2(wv, wv);
            fma2(a01, wd, h2.x);
            fma2(a23, wd, h2.y);
        }
        float2 f01 = unpack2(a01);
        float2 f23 = unpack2(a23);
        sg[0][g] = f01.x; sg[1][g] = f01.y; sg[2][g] = f23.x; sg[3][g] = f23.y;
        __syncthreads();
        if (so < nv) {
            float iv = sg[so][d];
            float fv = sg[so][d + HH];
            float gv = sg[so][d + 2 * HH];
            float ov = sg[so][d + 3 * HH];
            float cn = sigm(fv) * creg + sigm(iv) * tanhf(gv);
            float hn = sigm(ov) * tanhf(cn);
            creg = cn;
            shT[d][so] = hn;
            d_Hcat[((size_t)(s0 + so) * TT + t) * HDIM + dir * HH + d] = hn;
        }
        __syncthreads();
    }
}

/* ------------------------------ BiDAF + score ------------------------------ */
__global__ void att_kernel(const float* __restrict__ wc, const float* __restrict__ bc,
                           const float* __restrict__ wq, const float* __restrict__ bq,
                           const float* __restrict__ wcq, const float* __restrict__ bcq,
                           const float* __restrict__ wz, const float* __restrict__ bz) {
    int b = blockIdx.x;
    int pair = blockIdx.y;
    int tid = threadIdx.x;
    int cseq = pair ? 192 : 128 + b;
    int qseq = pair ? 64 + b : b;
    const float* Cg = d_Hcat + (size_t)cseq * TT * HDIM;
    const float* Qg = d_Hcat + (size_t)qseq * TT * HDIM;
    __shared__ float CS[TT * HDIM];
    __shared__ float S[TT * TT];
    __shared__ float Aw[TT * TT];
    __shared__ float CD[TT], QD[TT], SMX[TT], BV[TT];
    __shared__ float Q2C[HDIM];
    __shared__ float RED[8];
    for (int i = tid; i < TT * HDIM; i += 256) CS[i] = Cg[i];
    __syncthreads();
    if (tid < TT) {
        float s = 0.f;
        const float* crow = CS + tid * HDIM;
        for (int d = 0; d < HDIM; d++) s += crow[d] * wc[d];
        CD[tid] = s;
    } else if (tid < 2 * TT) {
        int j = tid - TT;
        float s = 0.f;
        const float* qrow = Qg + (size_t)j * HDIM;
        for (int d = 0; d < HDIM; d++) s += qrow[d] * wq[d];
        QD[j] = s;
    }
    __syncthreads();
    float bsum = bc[0] + bq[0] + bcq[0];
#pragma unroll
    for (int r = 0; r < 4; r++) {
        int pi = tid * 4 + r;
        int i = pi >> 5, j = pi & 31;
        const float* crow = CS + i * HDIM;
        const float* qrow = Qg + (size_t)j * HDIM;
        float s = 0.f;
        for (int d = 0; d < HDIM; d++) s += crow[d] * qrow[d] * wcq[d];
        S[pi] = s + CD[i] + QD[j] + bsum;
    }
    __syncthreads();
    int lane = tid & 31, warp = tid >> 5;
    for (int i = warp; i < TT; i += 8) {
        float v = S[i * 32 + lane];
        float mx = v;
        for (int o = 16; o; o >>= 1) mx = fmaxf(mx, __shfl_xor_sync(0xffffffffu, mx, o));
        float e = expf(v - mx);
        float sm = e;
        for (int o = 16; o; o >>= 1) sm += __shfl_xor_sync(0xffffffffu, sm, o);
        Aw[i * 32 + lane] = e / sm;
        if (lane == 0) SMX[i] = mx;
    }
    __syncthreads();
    if (warp == 0) {
        float v = SMX[lane];
        float mx = v;
        for (int o = 16; o; o >>= 1) mx = fmaxf(mx, __shfl_xor_sync(0xffffffffu, mx, o));
        float e = expf(v - mx);
        float sm = e;
        for (int o = 16; o; o >>= 1) sm += __shfl_xor_sync(0xffffffffu, sm, o);
        BV[lane] = e / sm;
    }
    __syncthreads();
    {
        float s = 0.f;
        for (int i = 0; i < TT; i++) s += BV[i] * CS[i * HDIM + tid];
        Q2C[tid] = s;
    }
    __syncthreads();
    float bzv = bz[0];
    for (int i = 0; i < TT; i++) {
        int d = tid;
        float c2q = 0.f;
        for (int j = 0; j < TT; j++) c2q += Aw[i * 32 + j] * Qg[(size_t)j * HDIM + d];
        float cv = CS[i * HDIM + d];
        float term = cv * wz[d] + c2q * wz[HDIM + d] + cv * c2q * wz[2 * HDIM + d]
                   + cv * Q2C[d] * wz[3 * HDIM + d];
        for (int o = 16; o; o >>= 1) term += __shfl_xor_sync(0xffffffffu, term, o);
        if (lane == 0) RED[warp] = term;
        __syncthreads();
        if (tid == 0) {
            float tot = 0.f;
            for (int w2 = 0; w2 < 8; w2++) tot += RED[w2];
            d_p[(pair * MENT + b) * KCAND + i] = tot + bzv;
        }
        __syncthreads();
    }
}

__global__ void zero_kernel(float* __restrict__ out, int n) {
    int idx = blockIdx.x * blockDim.x + threadIdx.x;
    if (idx < n) out[idx] = 0.f;
}

__global__ void score_kernel(const int* __restrict__ cand,
                             const float* __restrict__ wp1, const float* __restrict__ bp1,
                             const float* __restrict__ wp2, const float* __restrict__ bp2,
                             float* __restrict__ out) {
    int b = blockIdx.x, i = threadIdx.x;
    float p1 = d_p[(0 * MENT + b) * KCAND + i];
    float p2 = d_p[(1 * MENT + b) * KCAND + i];
    float sc = wp1[0] * p1 + bp1[0] + wp2[0] * p2 + bp2[0];
    float mx = sc;
    for (int o = 16; o; o >>= 1) mx = fmaxf(mx, __shfl_xor_sync(0xffffffffu, mx, o));
    float e = expf(sc - mx);
    float es = e;
    for (int o = 16; o; o >>= 1) es += __shfl_xor_sync(0xffffffffu, es, o);
    float ssum = sc;
    for (int o = 16; o; o >>= 1) ssum += __shfl_xor_sync(0xffffffffu, ssum, o);
    int col = cand[b * KCAND + i];
    out[(size_t)b * N_ENT + col] = sc;
    out[(size_t)MENT * N_ENT + (size_t)b * N_ENT + col] = e / es;
    out[(size_t)2 * MENT * N_ENT + (size_t)b * N_ENT + col] = sc / ssum;
}

/* ------------------------------- launcher ---------------------------------- */
extern "C" void kernel_launch(void* const* d_in, const int* in_sizes, int n_in,
                              void* d_out, int out_size) {
    const int*   title  = (const int*)d_in[0];
    const int*   body   = (const int*)d_in[1];
    const int*   ctx    = (const int*)d_in[3];
    const int*   doc    = (const int*)d_in[4];
    const int*   cand   = (const int*)d_in[5];
    const float* emb    = (const float*)d_in[6];
    const float* conv_w = (const float*)d_in[7];
    const float* conv_b = (const float*)d_in[8];
    const float* Wih_f  = (const float*)d_in[9];
    const float* Whh_f  = (const float*)d_in[10];
    const float* bih_f  = (const float*)d_in[11];
    const float* bhh_f  = (const float*)d_in[12];
    const float* Wih_b  = (const float*)d_in[13];
    const float* Whh_b  = (const float*)d_in[14];
    const float* bih_b  = (const float*)d_in[15];
    const float* bhh_b  = (const float*)d_in[16];
    const float* wc  = (const float*)d_in[17];
    const float* bc  = (const float*)d_in[18];
    const float* wq  = (const float*)d_in[19];
    const float* bq  = (const float*)d_in[20];
    const float* wcq = (const float*)d_in[21];
    const float* bcq = (const float*)d_in[22];
    const float* wz  = (const float*)d_in[23];
    const float* bz  = (const float*)d_in[24];
    const float* wp1 = (const float*)d_in[25];
    const float* bp1 = (const float*)d_in[26];
    const float* wp2 = (const float*)d_in[27];
    const float* bp2 = (const float*)d_in[28];
    float* out = (float*)d_out;
    (void)in_sizes; (void)n_in; (void)out_size;

    float *pT, *pB, *pE, *pF, *pWT, *pPre;
    cudaGetSymbolAddress((void**)&pT, d_T);
    cudaGetSymbolAddress((void**)&pB, d_Bmat);
    cudaGetSymbolAddress((void**)&pE, d_embP);
    cudaGetSymbolAddress((void**)&pF, d_F);
    cudaGetSymbolAddress((void**)&pWT, d_WihT);
    cudaGetSymbolAddress((void**)&pPre, d_preAll);

    static int smem_set = 0;
    if (!smem_set) {
        cudaFuncSetAttribute(lstm_kernel, cudaFuncAttributeMaxDynamicSharedMemorySize,
                             WCACHE * G4 * (int)sizeof(float));
        smem_set = 1;
    }

    /* 1: reset used flags + counter */
    prep0_kernel<<<(N_ENT + 256) / 256, 256>>>();

    /* 2: transposes / padded fills / used-entity scatter */
    prep1_kernel<<<(PTOT + 255) / 256, 256>>>(emb, conv_w, Wih_f, Wih_b, Whh_f, Whh_b, cand);

    /* 3: compact entity list + positions */
    prep2_kernel<<<(N_ENT + 255) / 256, 256>>>();

    /* 4: LSTM row index table (compact rows) */
    prep3_kernel<<<(NSEQ * TT + 255) / 256, 256>>>(cand);

    /* 5: zero output */
    {
        int n = 3 * MENT * N_ENT;
        zero_kernel<<<(n + 255) / 256, 256>>>(out, n);
    }

    /* 6: token table T = embP @ BmatP : [5120 x 2560], K=304 */
    sgemm_k<<<dim3(WNC / 128, VOCABP / 128), 256>>>(pE, pB, pT, WNC, EMBP, EMBP / 16, 0);

    /* 7: char-CNN features (used entities only) */
    conv_all<<<1 + N_ENT + MENT + N_ENT, 256>>>(title, body, ctx, doc, conv_b);

    /* 8: pre-activations: [4224 x 1024], K=512, dead row-blocks skipped */
    sgemm_k<<<dim3(GCAT / 128, NFEATP / 128), 256>>>(pF, pWT, pPre, GCAT, CCS, CCS / 16, 1);

    /* 9: recurrence */
    lstm_kernel<<<dim3((NSEQ + 3) / 4, 2), 512, WCACHE * G4 * sizeof(float)>>>(
        bih_f, bhh_f, bih_b, bhh_b);

    /* 10: BiDAF attention + projection */
    att_kernel<<<dim3(MENT, 2), 256>>>(wc, bc, wq, bq, wcq, bcq, wz, bz);

    /* 11: score, softmax, sum-normalize, scatter */
    score_kernel<<<MENT, KCAND>>>(cand, wp1, bp1, wp2, bp2, out);
}

// round 15
// speedup vs baseline: 1.3892x; 1.3015x over previous
#include <cuda_runtime.h>
#include <cuda_bf16.h>
#include <math.h>
#include <stddef.h>
#include <stdint.h>

#define N_ENT 2048
#define MENT  64
#define KCAND 32
#define LT 32
#define LB 128
#define LC 128
#define LD 512
#define VOCAB 5053
#define VOCABP 5120
#define EMB 300
#define KP1 320
#define HDIM 256
#define HH 128
#define CCS 512
#define WIN 5
#define NSEQ 193
#define TT 32
#define G4 512
#define GCAT 1024
#define NFEATP 4224
#define WNC (WIN * CCS)        /* 2560 */
#define WCACHE 96
#define SSTR 40                /* smem row stride in bf16 (80B, conflict-free) */

typedef unsigned long long ull;

/* ------------------------- scratch (device globals) ------------------------ */
__device__ float d_T[(size_t)VOCABP * WNC];
__device__ __nv_bfloat16 d_embH[(size_t)VOCABP * KP1];
__device__ __nv_bfloat16 d_embL[(size_t)VOCABP * KP1];
__device__ __nv_bfloat16 d_BmtH[(size_t)WNC * KP1];
__device__ __nv_bfloat16 d_BmtL[(size_t)WNC * KP1];
__device__ __nv_bfloat16 d_FH[(size_t)NFEATP * CCS];
__device__ __nv_bfloat16 d_FL[(size_t)NFEATP * CCS];
__device__ __nv_bfloat16 d_WcH[(size_t)GCAT * CCS];
__device__ __nv_bfloat16 d_WcL[(size_t)GCAT * CCS];
__device__ float d_preAll[(size_t)NFEATP * GCAT];
__device__ int   d_rowIdx[NSEQ * TT];
__device__ float d_WhhT_f[HH * G4];
__device__ float d_WhhT_b[HH * G4];
__device__ float d_Hcat[NSEQ * TT * HDIM];
__device__ float d_p[2 * MENT * KCAND];
__device__ int   d_used[N_ENT];
__device__ int   d_pos[N_ENT];
__device__ int   d_list[N_ENT];
__device__ int   d_nU[1];

__device__ __forceinline__ float sigm(float x) { return 1.f / (1.f + expf(-x)); }

__device__ __forceinline__ void fma2(ull &d, ull a, ull b) {
    asm("fma.rn.f32x2 %0, %1, %2, %0;" : "+l"(d) : "l"(a), "l"(b));
}
__device__ __forceinline__ ull pack2(float lo, float hi) {
    ull r; asm("mov.b64 %0, {%1, %2};" : "=l"(r) : "f"(lo), "f"(hi)); return r;
}
__device__ __forceinline__ float2 unpack2(ull v) {
    float2 f; asm("mov.b64 {%0, %1}, %2;" : "=f"(f.x), "=f"(f.y) : "l"(v)); return f;
}
__device__ __forceinline__ uint32_t smem_u32(const void* p) {
    uint32_t a;
    asm("{ .reg .u64 t; cvta.to.shared.u64 t, %1; cvt.u32.u64 %0, t; }" : "=r"(a) : "l"(p));
    return a;
}
__device__ __forceinline__ void split_bf16(float x, __nv_bfloat16& h, __nv_bfloat16& l) {
    h = __float2bfloat16_rn(x);
    l = __float2bfloat16_rn(x - __bfloat162float(h));
}

#define LDSM_X4(r, addr) \
    asm volatile("ldmatrix.sync.aligned.m8n8.x4.shared.b16 {%0,%1,%2,%3}, [%4];" \
        : "=r"((r)[0]), "=r"((r)[1]), "=r"((r)[2]), "=r"((r)[3]) : "r"(addr))
#define LDSM_X2(r, addr) \
    asm volatile("ldmatrix.sync.aligned.m8n8.x2.shared.b16 {%0,%1}, [%2];" \
        : "=r"((r)[0]), "=r"((r)[1]) : "r"(addr))
#define MMA_BF16(c, a, b) \
    asm volatile("mma.sync.aligned.m16n8k16.row.col.f32.bf16.bf16.f32 " \
        "{%0,%1,%2,%3}, {%4,%5,%6,%7}, {%8,%9}, {%0,%1,%2,%3};" \
        : "+f"((c)[0]), "+f"((c)[1]), "+f"((c)[2]), "+f"((c)[3]) \
        : "r"((a)[0]), "r"((a)[1]), "r"((a)[2]), "r"((a)[3]), "r"((b)[0]), "r"((b)[1]))

/* ------------------------------ prep kernels ------------------------------- */
__global__ void prep0_kernel() {
    int i = blockIdx.x * 256 + threadIdx.x;
    if (i < N_ENT) d_used[i] = 0;
    if (i == N_ENT) d_nU[0] = 0;
}

#define P_EMB (VOCABP * KP1)
#define P_BMT (WNC * KP1)
#define P_WIH (GCAT * CCS)
#define P_WHH (2 * G4 * HH)
#define P_USED (MENT * KCAND)
#define PTOT (P_EMB + P_BMT + P_WIH + P_WHH + P_USED)

__global__ void prep1_kernel(const float* __restrict__ emb,
                             const float* __restrict__ conv_w,
                             const float* __restrict__ Wih_f, const float* __restrict__ Wih_b,
                             const float* __restrict__ Whh_f, const float* __restrict__ Whh_b,
                             const int* __restrict__ cand) {
    int idx = blockIdx.x * 256 + threadIdx.x;
    if (idx < P_EMB) {
        int r = idx / KP1, k = idx % KP1;
        float v = (r < VOCAB && k < EMB) ? emb[r * EMB + k] : 0.f;
        __nv_bfloat16 h, l; split_bf16(v, h, l);
        d_embH[idx] = h; d_embL[idx] = l;
        return;
    }
    idx -= P_EMB;
    if (idx < P_BMT) {
        int n = idx / KP1, k = idx % KP1;
        int w = n / CCS, c = n % CCS;
        float v = (k < EMB) ? conv_w[c * (EMB * WIN) + k * WIN + w] : 0.f;
        __nv_bfloat16 h, l; split_bf16(v, h, l);
        d_BmtH[idx] = h; d_BmtL[idx] = l;
        return;
    }
    idx -= P_BMT;
    if (idx < P_WIH) {
        int n = idx / CCS, k = idx % CCS;
        int dir = n >> 9, g = n & 511;
        float v = (dir ? Wih_b : Wih_f)[g * CCS + k];
        __nv_bfloat16 h, l; split_bf16(v, h, l);
        d_WcH[idx] = h; d_WcL[idx] = l;
        return;
    }
    idx -= P_WIH;
    if (idx < P_WHH) {
        int dir = idx / (G4 * HH);
        int rem = idx % (G4 * HH);
        int g = rem / HH, j = rem % HH;
        float* dst = dir ? d_WhhT_b : d_WhhT_f;
        dst[j * G4 + g] = (dir ? Whh_b : Whh_f)[rem];
        return;
    }
    idx -= P_WHH;
    if (idx < P_USED) d_used[cand[idx]] = 1;
}

__global__ void prep2_kernel() {
    int i = blockIdx.x * 256 + threadIdx.x;
    if (i < N_ENT && d_used[i]) {
        int p = atomicAdd(&d_nU[0], 1);
        d_pos[i] = p;
        d_list[p] = i;
    }
}

__global__ void prep3_kernel(const int* __restrict__ cand) {
    int idx = blockIdx.x * 256 + threadIdx.x;
    if (idx >= NSEQ * TT) return;
    int seq = idx / TT, t = idx % TT;
    int r;
    if (seq < 64)       r = d_pos[cand[seq * TT + t]];
    else if (seq < 128) r = 2048 + d_pos[cand[(seq - 64) * TT + t]];
    else if (seq < 192) r = 4096 + (seq - 128);
    else                r = 4160;
    d_rowIdx[idx] = r;
}

/* ---------------- mma.sync bf16-split GEMM: C = A @ B^T -------------------- */
/* A (hi/lo): [M x Kp] bf16 K-major. B (hi/lo): [Np x Kp] bf16 K-major.
   C fp32 [M x Np]. Block 128x128, 8 warps, warp tile 64x32, K-chunk 32.
   3-MMA hi/lo split per tile.                                                */
__global__ void __launch_bounds__(256, 2) mma_gemm(
        const __nv_bfloat16* __restrict__ Ah, const __nv_bfloat16* __restrict__ Al,
        const __nv_bfloat16* __restrict__ Bh, const __nv_bfloat16* __restrict__ Bl,
        float* __restrict__ C, int Kp, int Np, int nChunk, int rowfilter) {
    __shared__ __align__(16) __nv_bfloat16 sAh[128 * SSTR];
    __shared__ __align__(16) __nv_bfloat16 sAl[128 * SSTR];
    __shared__ __align__(16) __nv_bfloat16 sBh[128 * SSTR];
    __shared__ __align__(16) __nv_bfloat16 sBl[128 * SSTR];
    int tid = threadIdx.x;
    int wid = tid >> 5, lane = tid & 31;
    int wm = wid >> 2, wn = wid & 3;       /* warp grid 2x4 */
    int m0 = blockIdx.y * 128, n0 = blockIdx.x * 128;
    if (rowfilter) {
        int nU = d_nU[0];
        bool act = (m0 < nU) || (m0 + 128 > 2048 && m0 < 2048 + nU) || (m0 + 128 > 4096);
        if (!act) return;
    }
    float c[4][4][4];
#pragma unroll
    for (int mt = 0; mt < 4; mt++)
#pragma unroll
        for (int nt = 0; nt < 4; nt++)
#pragma unroll
            for (int q = 0; q < 4; q++) c[mt][nt][q] = 0.f;

    /* per-thread copy coords: 512 uint4 per tile, 2/thread */
    int cRow0 = tid >> 1, cQ0 = (tid & 1) * 2;     /* two uint4 -> q = cQ0, cQ0+1 */

    /* ldmatrix smem row/col selectors (per lane) */
    uint32_t aRowSel = lane & 15;
    uint32_t aColSel = (lane >> 4) << 3;           /* 0 or 8 bf16 */
    uint32_t bRowSel = lane & 7;
    uint32_t bColSel = ((lane >> 3) & 1) << 3;

    for (int ch = 0; ch < nChunk; ch++) {
        int k0 = ch * 32;
#pragma unroll
        for (int r = 0; r < 2; r++) {
            int q = cQ0 + r;                       /* 0..3 */
            size_t ga = (size_t)(m0 + cRow0) * Kp + k0 + q * 8;
            size_t gb = (size_t)(n0 + cRow0) * Kp + k0 + q * 8;
            int sm = cRow0 * SSTR + q * 8;
            *(uint4*)&sAh[sm] = *(const uint4*)(Ah + ga);
            *(uint4*)&sAl[sm] = *(const uint4*)(Al + ga);
            *(uint4*)&sBh[sm] = *(const uint4*)(Bh + gb);
            *(uint4*)&sBl[sm] = *(const uint4*)(Bl + gb);
        }
        __syncthreads();
#pragma unroll
        for (int ks = 0; ks < 2; ks++) {
            uint32_t bh[4][2], bl[4][2];
#pragma unroll
            for (int nt = 0; nt < 4; nt++) {
                int brow = wn * 32 + nt * 8 + bRowSel;
                int bcol = ks * 16 + bColSel;
                uint32_t ab = smem_u32(&sBh[brow * SSTR + bcol]);
                LDSM_X2(bh[nt], ab);
                ab = smem_u32(&sBl[brow * SSTR + bcol]);
                LDSM_X2(bl[nt], ab);
            }
#pragma unroll
            for (int mt = 0; mt < 4; mt++) {
                uint32_t ah[4], al[4];
                int arow = wm * 64 + mt * 16 + aRowSel;
                int acol = ks * 16 + aColSel;
                uint32_t aa = smem_u32(&sAh[arow * SSTR + acol]);
                LDSM_X4(ah, aa);
                aa = smem_u32(&sAl[arow * SSTR + acol]);
                LDSM_X4(al, aa);
#pragma unroll
                for (int nt = 0; nt < 4; nt++) {
                    MMA_BF16(c[mt][nt], ah, bh[nt]);
                    MMA_BF16(c[mt][nt], ah, bl[nt]);
                    MMA_BF16(c[mt][nt], al, bh[nt]);
                }
            }
        }
        __syncthreads();
    }
    /* epilogue */
#pragma unroll
    for (int mt = 0; mt < 4; mt++) {
#pragma unroll
        for (int nt = 0; nt < 4; nt++) {
            int m = m0 + wm * 64 + mt * 16 + (lane >> 2);
            int n = n0 + wn * 32 + nt * 8 + (lane & 3) * 2;
            *(float2*)&C[(size_t)m * Np + n] = make_float2(c[mt][nt][0], c[mt][nt][1]);
            *(float2*)&C[(size_t)(m + 8) * Np + n] = make_float2(c[mt][nt][2], c[mt][nt][3]);
        }
    }
}

/* -------------------- conv via token table + maxpool ----------------------- */
__global__ void __launch_bounds__(256) conv_all(
        const int* __restrict__ title, const int* __restrict__ body,
        const int* __restrict__ ctx, const int* __restrict__ doc,
        const float* __restrict__ bias) {
    int blk = blockIdx.x;
    const int* toks; int L; int row;
    if (blk == 0) { toks = doc; L = LD; row = 4160; }
    else if (blk <= 2048) {
        int i = blk - 1;
        if (i >= d_nU[0]) return;
        toks = body + (size_t)d_list[i] * LB; L = LB; row = 2048 + i;
    } else if (blk <= 2112) {
        int i = blk - 2049;
        toks = ctx + (size_t)i * LC; L = LC; row = 4096 + i;
    } else {
        int i = blk - 2113;
        if (i >= d_nU[0]) return;
        toks = title + (size_t)d_list[i] * LT; L = LT; row = i;
    }
    int c2 = threadIdx.x;
    __shared__ int st[LD];
    for (int i = c2; i < L; i += 256) st[i] = toks[i];
    __syncthreads();
    float2 b = *(const float2*)&bias[2 * c2];
    float2 m = make_float2(0.f, 0.f);
    int P = L - WIN + 1;
    for (int p = 0; p < P; p++) {
        float2 acc = b;
#pragma unroll
        for (int w = 0; w < WIN; w++) {
            int v = st[p + w];
            float2 tv = *(const float2*)&d_T[((size_t)v * WIN + w) * CCS + 2 * c2];
            acc.x += tv.x; acc.y += tv.y;
        }
        m.x = fmaxf(m.x, acc.x);
        m.y = fmaxf(m.y, acc.y);
    }
    __nv_bfloat16 h0, l0, h1, l1;
    split_bf16(m.x, h0, l0);
    split_bf16(m.y, h1, l1);
    uint32_t hp = ((uint32_t)__bfloat16_as_ushort(h1) << 16) | __bfloat16_as_ushort(h0);
    uint32_t lp = ((uint32_t)__bfloat16_as_ushort(l1) << 16) | __bfloat16_as_ushort(l0);
    *(uint32_t*)&d_FH[(size_t)row * CCS + 2 * c2] = hp;
    *(uint32_t*)&d_FL[(size_t)row * CCS + 2 * c2] = lp;
}

/* ----------------------------- LSTM recurrence ----------------------------- */
__global__ void __launch_bounds__(512) lstm_kernel(
        const float* __restrict__ bih_f, const float* __restrict__ bhh_f,
        const float* __restrict__ bih_b, const float* __restrict__ bhh_b) {
    extern __shared__ float sW[];
    int dir = blockIdx.y;
    int s0 = blockIdx.x * 4;
    const float* WT = dir ? d_WhhT_b : d_WhhT_f;
    int g = threadIdx.x;
    float bias = dir ? (bih_b[g] + bhh_b[g]) : (bih_f[g] + bhh_f[g]);
    __shared__ float shT[HH][4];
    __shared__ float sg[4][G4];
    __shared__ int ridx[4][TT];
    int so = g >> 7, d = g & 127;
    float creg = 0.f;
    shT[d][so] = 0.f;
    for (int i = g; i < WCACHE * G4; i += 512) sW[i] = WT[i];
    for (int i = g; i < 4 * TT; i += 512) {
        int s = i >> 5, t = i & 31;
        int seq = s0 + s; if (seq >= NSEQ) seq = NSEQ - 1;
        ridx[s][t] = d_rowIdx[seq * TT + t];
    }
    __syncthreads();
    int nv = NSEQ - s0; if (nv > 4) nv = 4;
    const float* preBase = d_preAll + dir * G4 + g;
    for (int step = 0; step < TT; step++) {
        int t = dir ? (TT - 1 - step) : step;
        float p0 = preBase[(size_t)ridx[0][t] * GCAT] + bias;
        float p1 = preBase[(size_t)ridx[1][t] * GCAT] + bias;
        float p2 = preBase[(size_t)ridx[2][t] * GCAT] + bias;
        float p3 = preBase[(size_t)ridx[3][t] * GCAT] + bias;
        ull a01 = pack2(p0, p1);
        ull a23 = pack2(p2, p3);
#pragma unroll 8
        for (int j = 0; j < WCACHE; j++) {
            float wv = sW[j * G4 + g];
            ulonglong2 h2 = *(const ulonglong2*)&shT[j][0];
            ull wd = pack2(wv, wv);
            fma2(a01, wd, h2.x);
            fma2(a23, wd, h2.y);
        }
#pragma unroll 8
        for (int j = WCACHE; j < HH; j++) {
            float wv = __ldg(WT + (size_t)j * G4 + g);
            ulonglong2 h2 = *(const ulonglong2*)&shT[j][0];
            ull wd = pack2(wv, wv);
            fma2(a01, wd, h2.x);
            fma2(a23, wd, h2.y);
        }
        float2 f01 = unpack2(a01);
        float2 f23 = unpack2(a23);
        sg[0][g] = f01.x; sg[1][g] = f01.y; sg[2][g] = f23.x; sg[3][g] = f23.y;
        __syncthreads();
        if (so < nv) {
            float iv = sg[so][d];
            float fv = sg[so][d + HH];
            float gv = sg[so][d + 2 * HH];
            float ov = sg[so][d + 3 * HH];
            float cn = sigm(fv) * creg + sigm(iv) * tanhf(gv);
            float hn = sigm(ov) * tanhf(cn);
            creg = cn;
            shT[d][so] = hn;
            d_Hcat[((size_t)(s0 + so) * TT + t) * HDIM + dir * HH + d] = hn;
        }
        __syncthreads();
    }
}

/* ------------------------------ BiDAF + score ------------------------------ */
__global__ void att_kernel(const float* __restrict__ wc, const float* __restrict__ bc,
                           const float* __restrict__ wq, const float* __restrict__ bq,
                           const float* __restrict__ wcq, const float* __restrict__ bcq,
                           const float* __restrict__ wz, const float* __restrict__ bz) {
    int b = blockIdx.x;
    int pair = blockIdx.y;
    int tid = threadIdx.x;
    int cseq = pair ? 192 : 128 + b;
    int qseq = pair ? 64 + b : b;
    const float* Cg = d_Hcat + (size_t)cseq * TT * HDIM;
    const float* Qg = d_Hcat + (size_t)qseq * TT * HDIM;
    __shared__ float CS[TT * HDIM];
    __shared__ float S[TT * TT];
    __shared__ float Aw[TT * TT];
    __shared__ float CD[TT], QD[TT], SMX[TT], BV[TT];
    __shared__ float Q2C[HDIM];
    __shared__ float RED[8];
    for (int i = tid; i < TT * HDIM; i += 256) CS[i] = Cg[i];
    __syncthreads();
    if (tid < TT) {
        float s = 0.f;
        const float* crow = CS + tid * HDIM;
        for (int d = 0; d < HDIM; d++) s += crow[d] * wc[d];
        CD[tid] = s;
    } else if (tid < 2 * TT) {
        int j = tid - TT;
        float s = 0.f;
        const float* qrow = Qg + (size_t)j * HDIM;
        for (int d = 0; d < HDIM; d++) s += qrow[d] * wq[d];
        QD[j] = s;
    }
    __syncthreads();
    float bsum = bc[0] + bq[0] + bcq[0];
#pragma unroll
    for (int r = 0; r < 4; r++) {
        int pi = tid * 4 + r;
        int i = pi >> 5, j = pi & 31;
        const float* crow = CS + i * HDIM;
        const float* qrow = Qg + (size_t)j * HDIM;
        float s = 0.f;
        for (int d = 0; d < HDIM; d++) s += crow[d] * qrow[d] * wcq[d];
        S[pi] = s + CD[i] + QD[j] + bsum;
    }
    __syncthreads();
    int lane = tid & 31, warp = tid >> 5;
    for (int i = warp; i < TT; i += 8) {
        float v = S[i * 32 + lane];
        float mx = v;
        for (int o = 16; o; o >>= 1) mx = fmaxf(mx, __shfl_xor_sync(0xffffffffu, mx, o));
        float e = expf(v - mx);
        float sm = e;
        for (int o = 16; o; o >>= 1) sm += __shfl_xor_sync(0xffffffffu, sm, o);
        Aw[i * 32 + lane] = e / sm;
        if (lane == 0) SMX[i] = mx;
    }
    __syncthreads();
    if (warp == 0) {
        float v = SMX[lane];
        float mx = v;
        for (int o = 16; o; o >>= 1) mx = fmaxf(mx, __shfl_xor_sync(0xffffffffu, mx, o));
        float e = expf(v - mx);
        float sm = e;
        for (int o = 16; o; o >>= 1) sm += __shfl_xor_sync(0xffffffffu, sm, o);
        BV[lane] = e / sm;
    }
    __syncthreads();
    {
        float s = 0.f;
        for (int i = 0; i < TT; i++) s += BV[i] * CS[i * HDIM + tid];
        Q2C[tid] = s;
    }
    __syncthreads();
    float bzv = bz[0];
    for (int i = 0; i < TT; i++) {
        int d = tid;
        float c2q = 0.f;
        for (int j = 0; j < TT; j++) c2q += Aw[i * 32 + j] * Qg[(size_t)j * HDIM + d];
        float cv = CS[i * HDIM + d];
        float term = cv * wz[d] + c2q * wz[HDIM + d] + cv * c2q * wz[2 * HDIM + d]
                   + cv * Q2C[d] * wz[3 * HDIM + d];
        for (int o = 16; o; o >>= 1) term += __shfl_xor_sync(0xffffffffu, term, o);
        if (lane == 0) RED[warp] = term;
        __syncthreads();
        if (tid == 0) {
            float tot = 0.f;
            for (int w2 = 0; w2 < 8; w2++) tot += RED[w2];
            d_p[(pair * MENT + b) * KCAND + i] = tot + bzv;
        }
        __syncthreads();
    }
}

__global__ void zero_kernel(float* __restrict__ out, int n) {
    int idx = blockIdx.x * blockDim.x + threadIdx.x;
    if (idx < n) out[idx] = 0.f;
}

__global__ void score_kernel(const int* __restrict__ cand,
                             const float* __restrict__ wp1, const float* __restrict__ bp1,
                             const float* __restrict__ wp2, const float* __restrict__ bp2,
                             float* __restrict__ out) {
    int b = blockIdx.x, i = threadIdx.x;
    float p1 = d_p[(0 * MENT + b) * KCAND + i];
    float p2 = d_p[(1 * MENT + b) * KCAND + i];
    float sc = wp1[0] * p1 + bp1[0] + wp2[0] * p2 + bp2[0];
    float mx = sc;
    for (int o = 16; o; o >>= 1) mx = fmaxf(mx, __shfl_xor_sync(0xffffffffu, mx, o));
    float e = expf(sc - mx);
    float es = e;
    for (int o = 16; o; o >>= 1) es += __shfl_xor_sync(0xffffffffu, es, o);
    float ssum = sc;
    for (int o = 16; o; o >>= 1) ssum += __shfl_xor_sync(0xffffffffu, ssum, o);
    int col = cand[b * KCAND + i];
    out[(size_t)b * N_ENT + col] = sc;
    out[(size_t)MENT * N_ENT + (size_t)b * N_ENT + col] = e / es;
    out[(size_t)2 * MENT * N_ENT + (size_t)b * N_ENT + col] = sc / ssum;
}

/* ------------------------------- launcher ---------------------------------- */
extern "C" void kernel_launch(void* const* d_in, const int* in_sizes, int n_in,
                              void* d_out, int out_size) {
    const int*   title  = (const int*)d_in[0];
    const int*   body   = (const int*)d_in[1];
    const int*   ctx    = (const int*)d_in[3];
    const int*   doc    = (const int*)d_in[4];
    const int*   cand   = (const int*)d_in[5];
    const float* emb    = (const float*)d_in[6];
    const float* conv_w = (const float*)d_in[7];
    const float* conv_b = (const float*)d_in[8];
    const float* Wih_f  = (const float*)d_in[9];
    const float* Whh_f  = (const float*)d_in[10];
    const float* bih_f  = (const float*)d_in[11];
    const float* bhh_f  = (const float*)d_in[12];
    const float* Wih_b  = (const float*)d_in[13];
    const float* Whh_b  = (const float*)d_in[14];
    const float* bih_b  = (const float*)d_in[15];
    const float* bhh_b  = (const float*)d_in[16];
    const float* wc  = (const float*)d_in[17];
    const float* bc  = (const float*)d_in[18];
    const float* wq  = (const float*)d_in[19];
    const float* bq  = (const float*)d_in[20];
    const float* wcq = (const float*)d_in[21];
    const float* bcq = (const float*)d_in[22];
    const float* wz  = (const float*)d_in[23];
    const float* bz  = (const float*)d_in[24];
    const float* wp1 = (const float*)d_in[25];
    const float* bp1 = (const float*)d_in[26];
    const float* wp2 = (const float*)d_in[27];
    const float* bp2 = (const float*)d_in[28];
    float* out = (float*)d_out;
    (void)in_sizes; (void)n_in; (void)out_size;

    float *pT, *pPre;
    __nv_bfloat16 *pEH, *pEL, *pBH, *pBL, *pFH, *pFL, *pWH, *pWL;
    cudaGetSymbolAddress((void**)&pT, d_T);
    cudaGetSymbolAddress((void**)&pPre, d_preAll);
    cudaGetSymbolAddress((void**)&pEH, d_embH);
    cudaGetSymbolAddress((void**)&pEL, d_embL);
    cudaGetSymbolAddress((void**)&pBH, d_BmtH);
    cudaGetSymbolAddress((void**)&pBL, d_BmtL);
    cudaGetSymbolAddress((void**)&pFH, d_FH);
    cudaGetSymbolAddress((void**)&pFL, d_FL);
    cudaGetSymbolAddress((void**)&pWH, d_WcH);
    cudaGetSymbolAddress((void**)&pWL, d_WcL);

    static int attr_set = 0;
    if (!attr_set) {
        cudaFuncSetAttribute(lstm_kernel, cudaFuncAttributeMaxDynamicSharedMemorySize,
                             WCACHE * G4 * (int)sizeof(float));
        attr_set = 1;
    }

    /* 1-4: prep */
    prep0_kernel<<<(N_ENT + 256) / 256, 256>>>();
    prep1_kernel<<<(PTOT + 255) / 256, 256>>>(emb, conv_w, Wih_f, Wih_b, Whh_f, Whh_b, cand);
    prep2_kernel<<<(N_ENT + 255) / 256, 256>>>();
    prep3_kernel<<<(NSEQ * TT + 255) / 256, 256>>>(cand);

    /* 5: zero output */
    {
        int n = 3 * MENT * N_ENT;
        zero_kernel<<<(n + 255) / 256, 256>>>(out, n);
    }

    /* 6: token table T = emb @ Bmat^T : [5120 x 2560], K=320 (mma.sync) */
    mma_gemm<<<dim3(WNC / 128, VOCABP / 128), 256>>>(
        pEH, pEL, pBH, pBL, pT, KP1, WNC, KP1 / 32, 0);

    /* 7: char-CNN features (used entities only, bf16 hi/lo out) */
    conv_all<<<1 + N_ENT + MENT + N_ENT, 256>>>(title, body, ctx, doc, conv_b);

    /* 8: pre-activations = F @ Wih^T : [4224 x 1024], K=512 (mma.sync) */
    mma_gemm<<<dim3(GCAT / 128, NFEATP / 128), 256>>>(
        pFH, pFL, pWH, pWL, pPre, CCS, GCAT, CCS / 32, 1);

    /* 9: recurrence */
    lstm_kernel<<<dim3((NSEQ + 3) / 4, 2), 512, WCACHE * G4 * sizeof(float)>>>(
        bih_f, bhh_f, bih_b, bhh_b);

    /* 10: BiDAF attention + projection */
    att_kernel<<<dim3(MENT, 2), 256>>>(wc, bc, wq, bq, wcq, bcq, wz, bz);

    /* 11: score, softmax, sum-normalize, scatter */
    score_kernel<<<MENT, KCAND>>>(cand, wp1, bp1, wp2, bp2, out);
}

// round 16
// speedup vs baseline: 1.6551x; 1.1914x over previous
#include <cuda_runtime.h>
#include <cuda_bf16.h>
#include <cuda_fp16.h>
#include <math.h>
#include <stddef.h>
#include <stdint.h>

#define N_ENT 2048
#define MENT  64
#define KCAND 32
#define LT 32
#define LB 128
#define LC 128
#define LD 512
#define VOCAB 5053
#define VOCABP 5120
#define EMB 300
#define KP1 320
#define HDIM 256
#define HH 128
#define CCS 512
#define WIN 5
#define NSEQ 193
#define TT 32
#define G4 512
#define GCAT 1024
#define NFEATP 4224
#define WNC (WIN * CCS)        /* 2560 */
#define WCACHE 96
#define SSTR 40                /* smem row stride in bf16 (80B) */

typedef unsigned long long ull;

/* ------------------------- scratch (device globals) ------------------------ */
__device__ __half d_Th[(size_t)VOCABP * WNC];               /* fp16 token table */
__device__ __nv_bfloat16 d_embH[(size_t)VOCABP * KP1];
__device__ __nv_bfloat16 d_embL[(size_t)VOCABP * KP1];
__device__ __nv_bfloat16 d_BmtH[(size_t)WNC * KP1];
__device__ __nv_bfloat16 d_BmtL[(size_t)WNC * KP1];
__device__ __nv_bfloat16 d_FH[(size_t)NFEATP * CCS];
__device__ __nv_bfloat16 d_FL[(size_t)NFEATP * CCS];
__device__ __nv_bfloat16 d_WcH[(size_t)GCAT * CCS];
__device__ __nv_bfloat16 d_WcL[(size_t)GCAT * CCS];
__device__ float d_preAll[(size_t)NFEATP * GCAT];
__device__ int   d_rowIdx[NSEQ * TT];
__device__ float d_WhhT_f[HH * G4];
__device__ float d_WhhT_b[HH * G4];
__device__ float d_Hcat[NSEQ * TT * HDIM];
__device__ float d_p[2 * MENT * KCAND];
__device__ int   d_used[N_ENT];
__device__ int   d_pos[N_ENT];
__device__ int   d_list[N_ENT];
__device__ int   d_nU[1];

__device__ __forceinline__ float sigm(float x) { return 1.f / (1.f + expf(-x)); }

__device__ __forceinline__ void fma2(ull &d, ull a, ull b) {
    asm("fma.rn.f32x2 %0, %1, %2, %0;" : "+l"(d) : "l"(a), "l"(b));
}
__device__ __forceinline__ ull pack2(float lo, float hi) {
    ull r; asm("mov.b64 %0, {%1, %2};" : "=l"(r) : "f"(lo), "f"(hi)); return r;
}
__device__ __forceinline__ float2 unpack2(ull v) {
    float2 f; asm("mov.b64 {%0, %1}, %2;" : "=f"(f.x), "=f"(f.y) : "l"(v)); return f;
}
__device__ __forceinline__ uint32_t smem_u32(const void* p) {
    uint32_t a;
    asm("{ .reg .u64 t; cvta.to.shared.u64 t, %1; cvt.u32.u64 %0, t; }" : "=r"(a) : "l"(p));
    return a;
}
__device__ __forceinline__ void split_bf16(float x, __nv_bfloat16& h, __nv_bfloat16& l) {
    h = __float2bfloat16_rn(x);
    l = __float2bfloat16_rn(x - __bfloat162float(h));
}

#define LDSM_X4(r, addr) \
    asm volatile("ldmatrix.sync.aligned.m8n8.x4.shared.b16 {%0,%1,%2,%3}, [%4];" \
        : "=r"((r)[0]), "=r"((r)[1]), "=r"((r)[2]), "=r"((r)[3]) : "r"(addr))
#define LDSM_X2(r, addr) \
    asm volatile("ldmatrix.sync.aligned.m8n8.x2.shared.b16 {%0,%1}, [%2];" \
        : "=r"((r)[0]), "=r"((r)[1]) : "r"(addr))
#define MMA_BF16(c, a, b) \
    asm volatile("mma.sync.aligned.m16n8k16.row.col.f32.bf16.bf16.f32 " \
        "{%0,%1,%2,%3}, {%4,%5,%6,%7}, {%8,%9}, {%0,%1,%2,%3};" \
        : "+f"((c)[0]), "+f"((c)[1]), "+f"((c)[2]), "+f"((c)[3]) \
        : "r"((a)[0]), "r"((a)[1]), "r"((a)[2]), "r"((a)[3]), "r"((b)[0]), "r"((b)[1]))
#define CP_ASYNC16(saddr, gptr) \
    asm volatile("cp.async.cg.shared.global [%0], [%1], 16;" :: "r"(saddr), "l"(gptr))
#define CP_COMMIT() asm volatile("cp.async.commit_group;" ::: "memory")
#define CP_WAIT1()  asm volatile("cp.async.wait_group 1;" ::: "memory")
#define CP_WAIT0()  asm volatile("cp.async.wait_group 0;" ::: "memory")

/* ------------------------------ prep kernels ------------------------------- */
__global__ void prep0_kernel() {
    int i = blockIdx.x * 256 + threadIdx.x;
    if (i < N_ENT) d_used[i] = 0;
    if (i == N_ENT) d_nU[0] = 0;
}

#define P_EMB (VOCABP * KP1)
#define P_BMT (WNC * KP1)
#define P_WIH (GCAT * CCS)
#define P_WHH (2 * G4 * HH)
#define P_USED (MENT * KCAND)
#define PTOT (P_EMB + P_BMT + P_WIH + P_WHH + P_USED)

__global__ void prep1_kernel(const float* __restrict__ emb,
                             const float* __restrict__ conv_w,
                             const float* __restrict__ Wih_f, const float* __restrict__ Wih_b,
                             const float* __restrict__ Whh_f, const float* __restrict__ Whh_b,
                             const int* __restrict__ cand) {
    int idx = blockIdx.x * 256 + threadIdx.x;
    if (idx < P_EMB) {
        int r = idx / KP1, k = idx % KP1;
        float v = (r < VOCAB && k < EMB) ? emb[r * EMB + k] : 0.f;
        __nv_bfloat16 h, l; split_bf16(v, h, l);
        d_embH[idx] = h; d_embL[idx] = l;
        return;
    }
    idx -= P_EMB;
    if (idx < P_BMT) {
        int n = idx / KP1, k = idx % KP1;
        int w = n / CCS, c = n % CCS;
        float v = (k < EMB) ? conv_w[c * (EMB * WIN) + k * WIN + w] : 0.f;
        __nv_bfloat16 h, l; split_bf16(v, h, l);
        d_BmtH[idx] = h; d_BmtL[idx] = l;
        return;
    }
    idx -= P_BMT;
    if (idx < P_WIH) {
        int n = idx / CCS, k = idx % CCS;
        int dir = n >> 9, g = n & 511;
        float v = (dir ? Wih_b : Wih_f)[g * CCS + k];
        __nv_bfloat16 h, l; split_bf16(v, h, l);
        d_WcH[idx] = h; d_WcL[idx] = l;
        return;
    }
    idx -= P_WIH;
    if (idx < P_WHH) {
        int dir = idx / (G4 * HH);
        int rem = idx % (G4 * HH);
        int g = rem / HH, j = rem % HH;
        float* dst = dir ? d_WhhT_b : d_WhhT_f;
        dst[j * G4 + g] = (dir ? Whh_b : Whh_f)[rem];
        return;
    }
    idx -= P_WHH;
    if (idx < P_USED) d_used[cand[idx]] = 1;
}

__global__ void prep2_kernel() {
    int i = blockIdx.x * 256 + threadIdx.x;
    if (i < N_ENT && d_used[i]) {
        int p = atomicAdd(&d_nU[0], 1);
        d_pos[i] = p;
        d_list[p] = i;
    }
}

__global__ void prep3_kernel(const int* __restrict__ cand) {
    int idx = blockIdx.x * 256 + threadIdx.x;
    if (idx >= NSEQ * TT) return;
    int seq = idx / TT, t = idx % TT;
    int r;
    if (seq < 64)       r = d_pos[cand[seq * TT + t]];
    else if (seq < 128) r = 2048 + d_pos[cand[(seq - 64) * TT + t]];
    else if (seq < 192) r = 4096 + (seq - 128);
    else                r = 4160;
    d_rowIdx[idx] = r;
}

/* ---------------- mma.sync bf16-split GEMM: C = A @ B^T -------------------- */
/* Block 128x128, 8 warps, warp tile 64x32, K-chunk 32, cp.async 2-stage
   pipeline. halfOut: write fp16 instead of fp32.                             */
#define ABYTES (128 * SSTR * 2)    /* 10240 */
#define STAGEB (4 * ABYTES)        /* 40960 */
#define GEMM_SMEM (2 * STAGEB)     /* 81920 */

__global__ void __launch_bounds__(256, 2) mma_gemm(
        const __nv_bfloat16* __restrict__ Ah, const __nv_bfloat16* __restrict__ Al,
        const __nv_bfloat16* __restrict__ Bh, const __nv_bfloat16* __restrict__ Bl,
        void* __restrict__ Cv, int Kp, int Np, int nChunk, int rowfilter, int halfOut) {
    extern __shared__ __align__(16) char dsm[];
    uint32_t sb = smem_u32(dsm);
    int tid = threadIdx.x;
    int wid = tid >> 5, lane = tid & 31;
    int wm = wid >> 2, wn = wid & 3;
    int m0 = blockIdx.y * 128, n0 = blockIdx.x * 128;
    if (rowfilter) {
        int nU = d_nU[0];
        bool act = (m0 < nU) || (m0 + 128 > 2048 && m0 < 2048 + nU) || (m0 + 128 > 4096);
        if (!act) return;
    }
    float c[4][4][4];
#pragma unroll
    for (int mt = 0; mt < 4; mt++)
#pragma unroll
        for (int nt = 0; nt < 4; nt++)
#pragma unroll
            for (int q = 0; q < 4; q++) c[mt][nt][q] = 0.f;

    int cRow0 = tid >> 1, cQ0 = (tid & 1) * 2;
    uint32_t aRowSel = lane & 15;
    uint32_t aColSel = (lane >> 4) << 3;
    uint32_t bRowSel = lane & 7;
    uint32_t bColSel = ((lane >> 3) & 1) << 3;

#define ISSUE_CHUNK(ch, st) do { \
        uint32_t base_ = sb + (st) * STAGEB; \
        size_t koff_ = (size_t)(ch) * 32; \
        _Pragma("unroll") \
        for (int r_ = 0; r_ < 2; r_++) { \
            int q_ = cQ0 + r_; \
            size_t ga_ = (size_t)(m0 + cRow0) * Kp + koff_ + q_ * 8; \
            size_t gb_ = (size_t)(n0 + cRow0) * Kp + koff_ + q_ * 8; \
            uint32_t so_ = (uint32_t)((cRow0 * SSTR + q_ * 8) * 2); \
            CP_ASYNC16(base_ + 0 * ABYTES + so_, Ah + ga_); \
            CP_ASYNC16(base_ + 1 * ABYTES + so_, Al + ga_); \
            CP_ASYNC16(base_ + 2 * ABYTES + so_, Bh + gb_); \
            CP_ASYNC16(base_ + 3 * ABYTES + so_, Bl + gb_); \
        } \
        CP_COMMIT(); \
    } while (0)

    ISSUE_CHUNK(0, 0);
    if (nChunk > 1) ISSUE_CHUNK(1, 1);

    for (int ch = 0; ch < nChunk; ch++) {
        if (ch + 1 < nChunk) CP_WAIT1(); else CP_WAIT0();
        __syncthreads();
        uint32_t stBase = sb + (ch & 1) * STAGEB;
#pragma unroll
        for (int ks = 0; ks < 2; ks++) {
            uint32_t bh[4][2], bl[4][2];
#pragma unroll
            for (int nt = 0; nt < 4; nt++) {
                int brow = wn * 32 + nt * 8 + bRowSel;
                int bcol = ks * 16 + bColSel;
                uint32_t off = (uint32_t)((brow * SSTR + bcol) * 2);
                LDSM_X2(bh[nt], stBase + 2 * ABYTES + off);
                LDSM_X2(bl[nt], stBase + 3 * ABYTES + off);
            }
#pragma unroll
            for (int mt = 0; mt < 4; mt++) {
                uint32_t ah[4], al[4];
                int arow = wm * 64 + mt * 16 + aRowSel;
                int acol = ks * 16 + aColSel;
                uint32_t off = (uint32_t)((arow * SSTR + acol) * 2);
                LDSM_X4(ah, stBase + 0 * ABYTES + off);
                LDSM_X4(al, stBase + 1 * ABYTES + off);
#pragma unroll
                for (int nt = 0; nt < 4; nt++) {
                    MMA_BF16(c[mt][nt], ah, bh[nt]);
                    MMA_BF16(c[mt][nt], ah, bl[nt]);
                    MMA_BF16(c[mt][nt], al, bh[nt]);
                }
            }
        }
        __syncthreads();
        if (ch + 2 < nChunk) ISSUE_CHUNK(ch + 2, ch & 1);
    }
    /* epilogue */
    if (halfOut) {
        __half* H = (__half*)Cv;
#pragma unroll
        for (int mt = 0; mt < 4; mt++)
#pragma unroll
            for (int nt = 0; nt < 4; nt++) {
                int m = m0 + wm * 64 + mt * 16 + (lane >> 2);
                int n = n0 + wn * 32 + nt * 8 + (lane & 3) * 2;
                *(__half2*)&H[(size_t)m * Np + n] =
                    __floats2half2_rn(c[mt][nt][0], c[mt][nt][1]);
                *(__half2*)&H[(size_t)(m + 8) * Np + n] =
                    __floats2half2_rn(c[mt][nt][2], c[mt][nt][3]);
            }
    } else {
        float* C = (float*)Cv;
#pragma unroll
        for (int mt = 0; mt < 4; mt++)
#pragma unroll
            for (int nt = 0; nt < 4; nt++) {
                int m = m0 + wm * 64 + mt * 16 + (lane >> 2);
                int n = n0 + wn * 32 + nt * 8 + (lane & 3) * 2;
                *(float2*)&C[(size_t)m * Np + n] = make_float2(c[mt][nt][0], c[mt][nt][1]);
                *(float2*)&C[(size_t)(m + 8) * Np + n] = make_float2(c[mt][nt][2], c[mt][nt][3]);
            }
    }
}

/* -------------------- conv via fp16 token table + maxpool ------------------ */
__global__ void __launch_bounds__(256) conv_all(
        const int* __restrict__ title, const int* __restrict__ body,
        const int* __restrict__ ctx, const int* __restrict__ doc,
        const float* __restrict__ bias) {
    int blk = blockIdx.x;
    const int* toks; int L; int row;
    if (blk == 0) { toks = doc; L = LD; row = 4160; }
    else if (blk <= 2048) {
        int i = blk - 1;
        if (i >= d_nU[0]) return;
        toks = body + (size_t)d_list[i] * LB; L = LB; row = 2048 + i;
    } else if (blk <= 2112) {
        int i = blk - 2049;
        toks = ctx + (size_t)i * LC; L = LC; row = 4096 + i;
    } else {
        int i = blk - 2113;
        if (i >= d_nU[0]) return;
        toks = title + (size_t)d_list[i] * LT; L = LT; row = i;
    }
    int c2 = threadIdx.x;
    __shared__ int st[LD];
    for (int i = c2; i < L; i += 256) st[i] = toks[i];
    __syncthreads();
    float2 b = *(const float2*)&bias[2 * c2];
    float2 m = make_float2(0.f, 0.f);
    int P = L - WIN + 1;
    for (int p = 0; p < P; p++) {
        float2 acc = b;
#pragma unroll
        for (int w = 0; w < WIN; w++) {
            int v = st[p + w];
            __half2 tv = *(const __half2*)&d_Th[((size_t)v * WIN + w) * CCS + 2 * c2];
            float2 f = __half22float2(tv);
            acc.x += f.x; acc.y += f.y;
        }
        m.x = fmaxf(m.x, acc.x);
        m.y = fmaxf(m.y, acc.y);
    }
    __nv_bfloat16 h0, l0, h1, l1;
    split_bf16(m.x, h0, l0);
    split_bf16(m.y, h1, l1);
    uint32_t hp = ((uint32_t)__bfloat16_as_ushort(h1) << 16) | __bfloat16_as_ushort(h0);
    uint32_t lp = ((uint32_t)__bfloat16_as_ushort(l1) << 16) | __bfloat16_as_ushort(l0);
    *(uint32_t*)&d_FH[(size_t)row * CCS + 2 * c2] = hp;
    *(uint32_t*)&d_FL[(size_t)row * CCS + 2 * c2] = lp;
}

/* ----------------------------- LSTM recurrence ----------------------------- */
__global__ void __launch_bounds__(512) lstm_kernel(
        const float* __restrict__ bih_f, const float* __restrict__ bhh_f,
        const float* __restrict__ bih_b, const float* __restrict__ bhh_b) {
    extern __shared__ float sW[];
    int dir = blockIdx.y;
    int s0 = blockIdx.x * 4;
    const float* WT = dir ? d_WhhT_b : d_WhhT_f;
    int g = threadIdx.x;
    float bias = dir ? (bih_b[g] + bhh_b[g]) : (bih_f[g] + bhh_f[g]);
    __shared__ float shT[HH][4];
    __shared__ float sg[4][G4];
    __shared__ int ridx[4][TT];
    int so = g >> 7, d = g & 127;
    float creg = 0.f;
    shT[d][so] = 0.f;
    for (int i = g; i < WCACHE * G4; i += 512) sW[i] = WT[i];
    for (int i = g; i < 4 * TT; i += 512) {
        int s = i >> 5, t = i & 31;
        int seq = s0 + s; if (seq >= NSEQ) seq = NSEQ - 1;
        ridx[s][t] = d_rowIdx[seq * TT + t];
    }
    __syncthreads();
    int nv = NSEQ - s0; if (nv > 4) nv = 4;
    const float* preBase = d_preAll + dir * G4 + g;
    for (int step = 0; step < TT; step++) {
        int t = dir ? (TT - 1 - step) : step;
        float p0 = preBase[(size_t)ridx[0][t] * GCAT] + bias;
        float p1 = preBase[(size_t)ridx[1][t] * GCAT] + bias;
        float p2 = preBase[(size_t)ridx[2][t] * GCAT] + bias;
        float p3 = preBase[(size_t)ridx[3][t] * GCAT] + bias;
        ull a01 = pack2(p0, p1);
        ull a23 = pack2(p2, p3);
#pragma unroll 8
        for (int j = 0; j < WCACHE; j++) {
            float wv = sW[j * G4 + g];
            ulonglong2 h2 = *(const ulonglong2*)&shT[j][0];
            ull wd = pack2(wv, wv);
            fma2(a01, wd, h2.x);
            fma2(a23, wd, h2.y);
        }
#pragma unroll 8
        for (int j = WCACHE; j < HH; j++) {
            float wv = __ldg(WT + (size_t)j * G4 + g);
            ulonglong2 h2 = *(const ulonglong2*)&shT[j][0];
            ull wd = pack2(wv, wv);
            fma2(a01, wd, h2.x);
            fma2(a23, wd, h2.y);
        }
        float2 f01 = unpack2(a01);
        float2 f23 = unpack2(a23);
        sg[0][g] = f01.x; sg[1][g] = f01.y; sg[2][g] = f23.x; sg[3][g] = f23.y;
        __syncthreads();
        if (so < nv) {
            float iv = sg[so][d];
            float fv = sg[so][d + HH];
            float gv = sg[so][d + 2 * HH];
            float ov = sg[so][d + 3 * HH];
            float cn = sigm(fv) * creg + sigm(iv) * tanhf(gv);
            float hn = sigm(ov) * tanhf(cn);
            creg = cn;
            shT[d][so] = hn;
            d_Hcat[((size_t)(s0 + so) * TT + t) * HDIM + dir * HH + d] = hn;
        }
        __syncthreads();
    }
}

/* ------------------------------ BiDAF + score ------------------------------ */
__global__ void att_kernel(const float* __restrict__ wc, const float* __restrict__ bc,
                           const float* __restrict__ wq, const float* __restrict__ bq,
                           const float* __restrict__ wcq, const float* __restrict__ bcq,
                           const float* __restrict__ wz, const float* __restrict__ bz) {
    int b = blockIdx.x;
    int pair = blockIdx.y;
    int tid = threadIdx.x;
    int cseq = pair ? 192 : 128 + b;
    int qseq = pair ? 64 + b : b;
    const float* Cg = d_Hcat + (size_t)cseq * TT * HDIM;
    const float* Qg = d_Hcat + (size_t)qseq * TT * HDIM;
    __shared__ float CS[TT * HDIM];
    __shared__ float S[TT * TT];
    __shared__ float Aw[TT * TT];
    __shared__ float CD[TT], QD[TT], SMX[TT], BV[TT];
    __shared__ float Q2C[HDIM];
    __shared__ float RED[8];
    for (int i = tid; i < TT * HDIM; i += 256) CS[i] = Cg[i];
    __syncthreads();
    if (tid < TT) {
        float s = 0.f;
        const float* crow = CS + tid * HDIM;
        for (int d = 0; d < HDIM; d++) s += crow[d] * wc[d];
        CD[tid] = s;
    } else if (tid < 2 * TT) {
        int j = tid - TT;
        float s = 0.f;
        const float* qrow = Qg + (size_t)j * HDIM;
        for (int d = 0; d < HDIM; d++) s += qrow[d] * wq[d];
        QD[j] = s;
    }
    __syncthreads();
    float bsum = bc[0] + bq[0] + bcq[0];
#pragma unroll
    for (int r = 0; r < 4; r++) {
        int pi = tid * 4 + r;
        int i = pi >> 5, j = pi & 31;
        const float* crow = CS + i * HDIM;
        const float* qrow = Qg + (size_t)j * HDIM;
        float s = 0.f;
        for (int d = 0; d < HDIM; d++) s += crow[d] * qrow[d] * wcq[d];
        S[pi] = s + CD[i] + QD[j] + bsum;
    }
    __syncthreads();
    int lane = tid & 31, warp = tid >> 5;
    for (int i = warp; i < TT; i += 8) {
        float v = S[i * 32 + lane];
        float mx = v;
        for (int o = 16; o; o >>= 1) mx = fmaxf(mx, __shfl_xor_sync(0xffffffffu, mx, o));
        float e = expf(v - mx);
        float sm = e;
        for (int o = 16; o; o >>= 1) sm += __shfl_xor_sync(0xffffffffu, sm, o);
        Aw[i * 32 + lane] = e / sm;
        if (lane == 0) SMX[i] = mx;
    }
    __syncthreads();
    if (warp == 0) {
        float v = SMX[lane];
        float mx = v;
        for (int o = 16; o; o >>= 1) mx = fmaxf(mx, __shfl_xor_sync(0xffffffffu, mx, o));
        float e = expf(v - mx);
        float sm = e;
        for (int o = 16; o; o >>= 1) sm += __shfl_xor_sync(0xffffffffu, sm, o);
        BV[lane] = e / sm;
    }
    __syncthreads();
    {
        float s = 0.f;
        for (int i = 0; i < TT; i++) s += BV[i] * CS[i * HDIM + tid];
        Q2C[tid] = s;
    }
    __syncthreads();
    float bzv = bz[0];
    for (int i = 0; i < TT; i++) {
        int d = tid;
        float c2q = 0.f;
        for (int j = 0; j < TT; j++) c2q += Aw[i * 32 + j] * Qg[(size_t)j * HDIM + d];
        float cv = CS[i * HDIM + d];
        float term = cv * wz[d] + c2q * wz[HDIM + d] + cv * c2q * wz[2 * HDIM + d]
                   + cv * Q2C[d] * wz[3 * HDIM + d];
        for (int o = 16; o; o >>= 1) term += __shfl_xor_sync(0xffffffffu, term, o);
        if (lane == 0) RED[warp] = term;
        __syncthreads();
        if (tid == 0) {
            float tot = 0.f;
            for (int w2 = 0; w2 < 8; w2++) tot += RED[w2];
            d_p[(pair * MENT + b) * KCAND + i] = tot + bzv;
        }
        __syncthreads();
    }
}

__global__ void zero_kernel(float* __restrict__ out, int n) {
    int idx = blockIdx.x * blockDim.x + threadIdx.x;
    if (idx < n) out[idx] = 0.f;
}

__global__ void score_kernel(const int* __restrict__ cand,
                             const float* __restrict__ wp1, const float* __restrict__ bp1,
                             const float* __restrict__ wp2, const float* __restrict__ bp2,
                             float* __restrict__ out) {
    int b = blockIdx.x, i = threadIdx.x;
    float p1 = d_p[(0 * MENT + b) * KCAND + i];
    float p2 = d_p[(1 * MENT + b) * KCAND + i];
    float sc = wp1[0] * p1 + bp1[0] + wp2[0] * p2 + bp2[0];
    float mx = sc;
    for (int o = 16; o; o >>= 1) mx = fmaxf(mx, __shfl_xor_sync(0xffffffffu, mx, o));
    float e = expf(sc - mx);
    float es = e;
    for (int o = 16; o; o >>= 1) es += __shfl_xor_sync(0xffffffffu, es, o);
    float ssum = sc;
    for (int o = 16; o; o >>= 1) ssum += __shfl_xor_sync(0xffffffffu, ssum, o);
    int col = cand[b * KCAND + i];
    out[(size_t)b * N_ENT + col] = sc;
    out[(size_t)MENT * N_ENT + (size_t)b * N_ENT + col] = e / es;
    out[(size_t)2 * MENT * N_ENT + (size_t)b * N_ENT + col] = sc / ssum;
}

/* ------------------------------- launcher ---------------------------------- */
extern "C" void kernel_launch(void* const* d_in, const int* in_sizes, int n_in,
                              void* d_out, int out_size) {
    const int*   title  = (const int*)d_in[0];
    const int*   body   = (const int*)d_in[1];
    const int*   ctx    = (const int*)d_in[3];
    const int*   doc    = (const int*)d_in[4];
    const int*   cand   = (const int*)d_in[5];
    const float* emb    = (const float*)d_in[6];
    const float* conv_w = (const float*)d_in[7];
    const float* conv_b = (const float*)d_in[8];
    const float* Wih_f  = (const float*)d_in[9];
    const float* Whh_f  = (const float*)d_in[10];
    const float* bih_f  = (const float*)d_in[11];
    const float* bhh_f  = (const float*)d_in[12];
    const float* Wih_b  = (const float*)d_in[13];
    const float* Whh_b  = (const float*)d_in[14];
    const float* bih_b  = (const float*)d_in[15];
    const float* bhh_b  = (const float*)d_in[16];
    const float* wc  = (const float*)d_in[17];
    const float* bc  = (const float*)d_in[18];
    const float* wq  = (const float*)d_in[19];
    const float* bq  = (const float*)d_in[20];
    const float* wcq = (const float*)d_in[21];
    const float* bcq = (const float*)d_in[22];
    const float* wz  = (const float*)d_in[23];
    const float* bz  = (const float*)d_in[24];
    const float* wp1 = (const float*)d_in[25];
    const float* bp1 = (const float*)d_in[26];
    const float* wp2 = (const float*)d_in[27];
    const float* bp2 = (const float*)d_in[28];
    float* out = (float*)d_out;
    (void)in_sizes; (void)n_in; (void)out_size;

    void *pTh, *pPre;
    __nv_bfloat16 *pEH, *pEL, *pBH, *pBL, *pFH, *pFL, *pWH, *pWL;
    cudaGetSymbolAddress(&pTh, d_Th);
    cudaGetSymbolAddress(&pPre, d_preAll);
    cudaGetSymbolAddress((void**)&pEH, d_embH);
    cudaGetSymbolAddress((void**)&pEL, d_embL);
    cudaGetSymbolAddress((void**)&pBH, d_BmtH);
    cudaGetSymbolAddress((void**)&pBL, d_BmtL);
    cudaGetSymbolAddress((void**)&pFH, d_FH);
    cudaGetSymbolAddress((void**)&pFL, d_FL);
    cudaGetSymbolAddress((void**)&pWH, d_WcH);
    cudaGetSymbolAddress((void**)&pWL, d_WcL);

    static int attr_set = 0;
    if (!attr_set) {
        cudaFuncSetAttribute(lstm_kernel, cudaFuncAttributeMaxDynamicSharedMemorySize,
                             WCACHE * G4 * (int)sizeof(float));
        cudaFuncSetAttribute(mma_gemm, cudaFuncAttributeMaxDynamicSharedMemorySize,
                             GEMM_SMEM);
        attr_set = 1;
    }

    /* 1-4: prep */
    prep0_kernel<<<(N_ENT + 256) / 256, 256>>>();
    prep1_kernel<<<(PTOT + 255) / 256, 256>>>(emb, conv_w, Wih_f, Wih_b, Whh_f, Whh_b, cand);
    prep2_kernel<<<(N_ENT + 255) / 256, 256>>>();
    prep3_kernel<<<(NSEQ * TT + 255) / 256, 256>>>(cand);

    /* 5: zero output */
    {
        int n = 3 * MENT * N_ENT;
        zero_kernel<<<(n + 255) / 256, 256>>>(out, n);
    }

    /* 6: token table T(fp16) = emb @ Bmat^T : [5120 x 2560], K=320 */
    mma_gemm<<<dim3(WNC / 128, VOCABP / 128), 256, GEMM_SMEM>>>(
        pEH, pEL, pBH, pBL, pTh, KP1, WNC, KP1 / 32, 0, 1);

    /* 7: char-CNN features (used entities only, fp16 table reads) */
    conv_all<<<1 + N_ENT + MENT + N_ENT, 256>>>(title, body, ctx, doc, conv_b);

    /* 8: pre-activations = F @ Wih^T : [4224 x 1024], K=512, fp32 out */
    mma_gemm<<<dim3(GCAT / 128, NFEATP / 128), 256, GEMM_SMEM>>>(
        pFH, pFL, pWH, pWL, pPre, CCS, GCAT, CCS / 32, 1, 0);

    /* 9: recurrence */
    lstm_kernel<<<dim3((NSEQ + 3) / 4, 2), 512, WCACHE * G4 * sizeof(float)>>>(
        bih_f, bhh_f, bih_b, bhh_b);

    /* 10: BiDAF attention + projection */
    att_kernel<<<dim3(MENT, 2), 256>>>(wc, bc, wq, bq, wcq, bcq, wz, bz);

    /* 11: score, softmax, sum-normalize, scatter */
    score_kernel<<<MENT, KCAND>>>(cand, wp1, bp1, wp2, bp2, out);
}

// round 17
// speedup vs baseline: 1.7098x; 1.0331x over previous
#include <cuda_runtime.h>
#include <cuda_bf16.h>
#include <cuda_fp16.h>
#include <math.h>
#include <stddef.h>
#include <stdint.h>

#define N_ENT 2048
#define MENT  64
#define KCAND 32
#define LT 32
#define LB 128
#define LC 128
#define LD 512
#define VOCAB 5053
#define VOCABP 5120
#define EMB 300
#define KP1 320
#define HDIM 256
#define HH 128
#define CCS 512
#define WIN 5
#define NSEQ 193
#define TT 32
#define G4 512
#define GCAT 1024
#define NFEATP 4224
#define WNC (WIN * CCS)        /* 2560 */
#define WCACHE 96
#define SSTR 40                /* smem row stride in bf16 (80B) */

typedef unsigned long long ull;

/* ------------------------- scratch (device globals) ------------------------ */
__device__ __half d_Th[(size_t)VOCABP * WNC];               /* fp16 token table */
__device__ __nv_bfloat16 d_embH[(size_t)VOCABP * KP1];
__device__ __nv_bfloat16 d_embL[(size_t)VOCABP * KP1];
__device__ __nv_bfloat16 d_BmtH[(size_t)WNC * KP1];
__device__ __nv_bfloat16 d_BmtL[(size_t)WNC * KP1];
__device__ __nv_bfloat16 d_FH[(size_t)NFEATP * CCS];
__device__ __nv_bfloat16 d_FL[(size_t)NFEATP * CCS];
__device__ __nv_bfloat16 d_WcH[(size_t)GCAT * CCS];
__device__ __nv_bfloat16 d_WcL[(size_t)GCAT * CCS];
__device__ float d_preAll[(size_t)NFEATP * GCAT];
__device__ int   d_rowIdx[NSEQ * TT];
__device__ float d_WhhT_f[HH * G4];
__device__ float d_WhhT_b[HH * G4];
__device__ float d_Hcat[NSEQ * TT * HDIM];
__device__ float d_p[2 * MENT * KCAND];
__device__ int   d_used[N_ENT];
__device__ int   d_pos[N_ENT];
__device__ int   d_list[N_ENT];
__device__ int   d_nU[1];

__device__ __forceinline__ float sigm(float x) { return 1.f / (1.f + expf(-x)); }

__device__ __forceinline__ void fma2(ull &d, ull a, ull b) {
    asm("fma.rn.f32x2 %0, %1, %2, %0;" : "+l"(d) : "l"(a), "l"(b));
}
__device__ __forceinline__ ull pack2(float lo, float hi) {
    ull r; asm("mov.b64 %0, {%1, %2};" : "=l"(r) : "f"(lo), "f"(hi)); return r;
}
__device__ __forceinline__ float2 unpack2(ull v) {
    float2 f; asm("mov.b64 {%0, %1}, %2;" : "=f"(f.x), "=f"(f.y) : "l"(v)); return f;
}
__device__ __forceinline__ uint32_t smem_u32(const void* p) {
    uint32_t a;
    asm("{ .reg .u64 t; cvta.to.shared.u64 t, %1; cvt.u32.u64 %0, t; }" : "=r"(a) : "l"(p));
    return a;
}
__device__ __forceinline__ void split_bf16(float x, __nv_bfloat16& h, __nv_bfloat16& l) {
    h = __float2bfloat16_rn(x);
    l = __float2bfloat16_rn(x - __bfloat162float(h));
}

#define LDSM_X4(r, addr) \
    asm volatile("ldmatrix.sync.aligned.m8n8.x4.shared.b16 {%0,%1,%2,%3}, [%4];" \
        : "=r"((r)[0]), "=r"((r)[1]), "=r"((r)[2]), "=r"((r)[3]) : "r"(addr))
#define LDSM_X2(r, addr) \
    asm volatile("ldmatrix.sync.aligned.m8n8.x2.shared.b16 {%0,%1}, [%2];" \
        : "=r"((r)[0]), "=r"((r)[1]) : "r"(addr))
#define MMA_BF16(c, a, b) \
    asm volatile("mma.sync.aligned.m16n8k16.row.col.f32.bf16.bf16.f32 " \
        "{%0,%1,%2,%3}, {%4,%5,%6,%7}, {%8,%9}, {%0,%1,%2,%3};" \
        : "+f"((c)[0]), "+f"((c)[1]), "+f"((c)[2]), "+f"((c)[3]) \
        : "r"((a)[0]), "r"((a)[1]), "r"((a)[2]), "r"((a)[3]), "r"((b)[0]), "r"((b)[1]))
#define CP_ASYNC16(saddr, gptr) \
    asm volatile("cp.async.cg.shared.global [%0], [%1], 16;" :: "r"(saddr), "l"(gptr))
#define CP_COMMIT() asm volatile("cp.async.commit_group;" ::: "memory")
#define CP_WAIT1()  asm volatile("cp.async.wait_group 1;" ::: "memory")
#define CP_WAIT0()  asm volatile("cp.async.wait_group 0;" ::: "memory")

/* ------------------------------ prep kernels ------------------------------- */
__global__ void prep0_kernel() {
    int i = blockIdx.x * 256 + threadIdx.x;
    if (i < N_ENT) d_used[i] = 0;
    if (i == N_ENT) d_nU[0] = 0;
}

#define P_EMB (VOCABP * KP1)
#define P_BMT (WNC * KP1)
#define P_WIH (GCAT * CCS)
#define P_WHH (2 * G4 * HH)
#define P_USED (MENT * KCAND)
#define PTOT (P_EMB + P_BMT + P_WIH + P_WHH + P_USED)

__global__ void prep1_kernel(const float* __restrict__ emb,
                             const float* __restrict__ conv_w,
                             const float* __restrict__ Wih_f, const float* __restrict__ Wih_b,
                             const float* __restrict__ Whh_f, const float* __restrict__ Whh_b,
                             const int* __restrict__ cand) {
    int idx = blockIdx.x * 256 + threadIdx.x;
    if (idx < P_EMB) {
        int r = idx / KP1, k = idx % KP1;
        float v = (r < VOCAB && k < EMB) ? emb[r * EMB + k] : 0.f;
        __nv_bfloat16 h, l; split_bf16(v, h, l);
        d_embH[idx] = h; d_embL[idx] = l;
        return;
    }
    idx -= P_EMB;
    if (idx < P_BMT) {
        int n = idx / KP1, k = idx % KP1;
        int w = n / CCS, c = n % CCS;
        float v = (k < EMB) ? conv_w[c * (EMB * WIN) + k * WIN + w] : 0.f;
        __nv_bfloat16 h, l; split_bf16(v, h, l);
        d_BmtH[idx] = h; d_BmtL[idx] = l;
        return;
    }
    idx -= P_BMT;
    if (idx < P_WIH) {
        int n = idx / CCS, k = idx % CCS;
        int dir = n >> 9, g = n & 511;
        float v = (dir ? Wih_b : Wih_f)[g * CCS + k];
        __nv_bfloat16 h, l; split_bf16(v, h, l);
        d_WcH[idx] = h; d_WcL[idx] = l;
        return;
    }
    idx -= P_WIH;
    if (idx < P_WHH) {
        int dir = idx / (G4 * HH);
        int rem = idx % (G4 * HH);
        int g = rem / HH, j = rem % HH;
        float* dst = dir ? d_WhhT_b : d_WhhT_f;
        dst[j * G4 + g] = (dir ? Whh_b : Whh_f)[rem];
        return;
    }
    idx -= P_WHH;
    if (idx < P_USED) d_used[cand[idx]] = 1;
}

__global__ void prep2_kernel() {
    int i = blockIdx.x * 256 + threadIdx.x;
    if (i < N_ENT && d_used[i]) {
        int p = atomicAdd(&d_nU[0], 1);
        d_pos[i] = p;
        d_list[p] = i;
    }
}

__global__ void prep3_kernel(const int* __restrict__ cand) {
    int idx = blockIdx.x * 256 + threadIdx.x;
    if (idx >= NSEQ * TT) return;
    int seq = idx / TT, t = idx % TT;
    int r;
    if (seq < 64)       r = d_pos[cand[seq * TT + t]];
    else if (seq < 128) r = 2048 + d_pos[cand[(seq - 64) * TT + t]];
    else if (seq < 192) r = 4096 + (seq - 128);
    else                r = 4160;
    d_rowIdx[idx] = r;
}

/* ---------------- mma.sync bf16-split GEMM: C = A @ B^T -------------------- */
#define ABYTES (128 * SSTR * 2)    /* 10240 */
#define STAGEB (4 * ABYTES)        /* 40960 */
#define GEMM_SMEM (2 * STAGEB)     /* 81920 */

__global__ void __launch_bounds__(256, 2) mma_gemm(
        const __nv_bfloat16* __restrict__ Ah, const __nv_bfloat16* __restrict__ Al,
        const __nv_bfloat16* __restrict__ Bh, const __nv_bfloat16* __restrict__ Bl,
        void* __restrict__ Cv, int Kp, int Np, int nChunk, int rowfilter, int halfOut) {
    extern __shared__ __align__(16) char dsm[];
    uint32_t sb = smem_u32(dsm);
    int tid = threadIdx.x;
    int wid = tid >> 5, lane = tid & 31;
    int wm = wid >> 2, wn = wid & 3;
    int m0 = blockIdx.y * 128, n0 = blockIdx.x * 128;
    if (rowfilter) {
        int nU = d_nU[0];
        bool act = (m0 < nU) || (m0 + 128 > 2048 && m0 < 2048 + nU) || (m0 + 128 > 4096);
        if (!act) return;
    }
    float c[4][4][4];
#pragma unroll
    for (int mt = 0; mt < 4; mt++)
#pragma unroll
        for (int nt = 0; nt < 4; nt++)
#pragma unroll
            for (int q = 0; q < 4; q++) c[mt][nt][q] = 0.f;

    int cRow0 = tid >> 1, cQ0 = (tid & 1) * 2;
    uint32_t aRowSel = lane & 15;
    uint32_t aColSel = (lane >> 4) << 3;
    uint32_t bRowSel = lane & 7;
    uint32_t bColSel = ((lane >> 3) & 1) << 3;

#define ISSUE_CHUNK(ch, st) do { \
        uint32_t base_ = sb + (st) * STAGEB; \
        size_t koff_ = (size_t)(ch) * 32; \
        _Pragma("unroll") \
        for (int r_ = 0; r_ < 2; r_++) { \
            int q_ = cQ0 + r_; \
            size_t ga_ = (size_t)(m0 + cRow0) * Kp + koff_ + q_ * 8; \
            size_t gb_ = (size_t)(n0 + cRow0) * Kp + koff_ + q_ * 8; \
            uint32_t so_ = (uint32_t)((cRow0 * SSTR + q_ * 8) * 2); \
            CP_ASYNC16(base_ + 0 * ABYTES + so_, Ah + ga_); \
            CP_ASYNC16(base_ + 1 * ABYTES + so_, Al + ga_); \
            CP_ASYNC16(base_ + 2 * ABYTES + so_, Bh + gb_); \
            CP_ASYNC16(base_ + 3 * ABYTES + so_, Bl + gb_); \
        } \
        CP_COMMIT(); \
    } while (0)

    ISSUE_CHUNK(0, 0);
    if (nChunk > 1) ISSUE_CHUNK(1, 1);

    for (int ch = 0; ch < nChunk; ch++) {
        if (ch + 1 < nChunk) CP_WAIT1(); else CP_WAIT0();
        __syncthreads();
        uint32_t stBase = sb + (ch & 1) * STAGEB;
#pragma unroll
        for (int ks = 0; ks < 2; ks++) {
            uint32_t bh[4][2], bl[4][2];
#pragma unroll
            for (int nt = 0; nt < 4; nt++) {
                int brow = wn * 32 + nt * 8 + bRowSel;
                int bcol = ks * 16 + bColSel;
                uint32_t off = (uint32_t)((brow * SSTR + bcol) * 2);
                LDSM_X2(bh[nt], stBase + 2 * ABYTES + off);
                LDSM_X2(bl[nt], stBase + 3 * ABYTES + off);
            }
#pragma unroll
            for (int mt = 0; mt < 4; mt++) {
                uint32_t ah[4], al[4];
                int arow = wm * 64 + mt * 16 + aRowSel;
                int acol = ks * 16 + aColSel;
                uint32_t off = (uint32_t)((arow * SSTR + acol) * 2);
                LDSM_X4(ah, stBase + 0 * ABYTES + off);
                LDSM_X4(al, stBase + 1 * ABYTES + off);
#pragma unroll
                for (int nt = 0; nt < 4; nt++) {
                    MMA_BF16(c[mt][nt], ah, bh[nt]);
                    MMA_BF16(c[mt][nt], ah, bl[nt]);
                    MMA_BF16(c[mt][nt], al, bh[nt]);
                }
            }
        }
        __syncthreads();
        if (ch + 2 < nChunk) ISSUE_CHUNK(ch + 2, ch & 1);
    }
    if (halfOut) {
        __half* H = (__half*)Cv;
#pragma unroll
        for (int mt = 0; mt < 4; mt++)
#pragma unroll
            for (int nt = 0; nt < 4; nt++) {
                int m = m0 + wm * 64 + mt * 16 + (lane >> 2);
                int n = n0 + wn * 32 + nt * 8 + (lane & 3) * 2;
                *(__half2*)&H[(size_t)m * Np + n] =
                    __floats2half2_rn(c[mt][nt][0], c[mt][nt][1]);
                *(__half2*)&H[(size_t)(m + 8) * Np + n] =
                    __floats2half2_rn(c[mt][nt][2], c[mt][nt][3]);
            }
    } else {
        float* C = (float*)Cv;
#pragma unroll
        for (int mt = 0; mt < 4; mt++)
#pragma unroll
            for (int nt = 0; nt < 4; nt++) {
                int m = m0 + wm * 64 + mt * 16 + (lane >> 2);
                int n = n0 + wn * 32 + nt * 8 + (lane & 3) * 2;
                *(float2*)&C[(size_t)m * Np + n] = make_float2(c[mt][nt][0], c[mt][nt][1]);
                *(float2*)&C[(size_t)(m + 8) * Np + n] = make_float2(c[mt][nt][2], c[mt][nt][3]);
            }
    }
}

/* --------- conv via fp16 token table + maxpool (2-pos-parallel) ------------ */
/* 256 threads: cg = tid&127 handles 4 channels (8B loads); pp = tid>>7
   strides positions by 2. Halves the LDG count vs 2-ch/thread version.       */
__global__ void __launch_bounds__(256) conv_all(
        const int* __restrict__ title, const int* __restrict__ body,
        const int* __restrict__ ctx, const int* __restrict__ doc,
        const float* __restrict__ bias) {
    int blk = blockIdx.x;
    const int* toks; int L; int row;
    if (blk == 0) { toks = doc; L = LD; row = 4160; }
    else if (blk <= 2048) {
        int i = blk - 1;
        if (i >= d_nU[0]) return;
        toks = body + (size_t)d_list[i] * LB; L = LB; row = 2048 + i;
    } else if (blk <= 2112) {
        int i = blk - 2049;
        toks = ctx + (size_t)i * LC; L = LC; row = 4096 + i;
    } else {
        int i = blk - 2113;
        if (i >= d_nU[0]) return;
        toks = title + (size_t)d_list[i] * LT; L = LT; row = i;
    }
    int tid = threadIdx.x;
    int cg = tid & 127;            /* channel group of 4 */
    int pp = tid >> 7;             /* position parity 0/1 */
    __shared__ int st[LD];
    __shared__ float sred[128][4];
    for (int i = tid; i < L; i += 256) st[i] = toks[i];
    __syncthreads();
    float4 b4 = *(const float4*)&bias[cg * 4];
    float4 m = make_float4(0.f, 0.f, 0.f, 0.f);
    int P = L - WIN + 1;
    for (int p = pp; p < P; p += 2) {
        float4 acc = b4;
#pragma unroll
        for (int w = 0; w < WIN; w++) {
            int v = st[p + w];
            uint2 tv = *(const uint2*)&d_Th[((size_t)v * WIN + w) * CCS + cg * 4];
            float2 f0 = __half22float2(*(__half2*)&tv.x);
            float2 f1 = __half22float2(*(__half2*)&tv.y);
            acc.x += f0.x; acc.y += f0.y; acc.z += f1.x; acc.w += f1.y;
        }
        m.x = fmaxf(m.x, acc.x); m.y = fmaxf(m.y, acc.y);
        m.z = fmaxf(m.z, acc.z); m.w = fmaxf(m.w, acc.w);
    }
    if (pp == 1) { sred[cg][0] = m.x; sred[cg][1] = m.y; sred[cg][2] = m.z; sred[cg][3] = m.w; }
    __syncthreads();
    if (pp == 0) {
        m.x = fmaxf(m.x, sred[cg][0]); m.y = fmaxf(m.y, sred[cg][1]);
        m.z = fmaxf(m.z, sred[cg][2]); m.w = fmaxf(m.w, sred[cg][3]);
        __nv_bfloat16 h0, l0, h1, l1, h2, l2, h3, l3;
        split_bf16(m.x, h0, l0); split_bf16(m.y, h1, l1);
        split_bf16(m.z, h2, l2); split_bf16(m.w, h3, l3);
        uint2 hp, lp;
        hp.x = ((uint32_t)__bfloat16_as_ushort(h1) << 16) | __bfloat16_as_ushort(h0);
        hp.y = ((uint32_t)__bfloat16_as_ushort(h3) << 16) | __bfloat16_as_ushort(h2);
        lp.x = ((uint32_t)__bfloat16_as_ushort(l1) << 16) | __bfloat16_as_ushort(l0);
        lp.y = ((uint32_t)__bfloat16_as_ushort(l3) << 16) | __bfloat16_as_ushort(l2);
        *(uint2*)&d_FH[(size_t)row * CCS + cg * 4] = hp;
        *(uint2*)&d_FL[(size_t)row * CCS + cg * 4] = lp;
    }
}

/* ----------------------------- LSTM recurrence ----------------------------- */
__global__ void __launch_bounds__(512) lstm_kernel(
        const float* __restrict__ bih_f, const float* __restrict__ bhh_f,
        const float* __restrict__ bih_b, const float* __restrict__ bhh_b) {
    extern __shared__ float sW[];
    int dir = blockIdx.y;
    int s0 = blockIdx.x * 4;
    const float* WT = dir ? d_WhhT_b : d_WhhT_f;
    int g = threadIdx.x;
    float bias = dir ? (bih_b[g] + bhh_b[g]) : (bih_f[g] + bhh_f[g]);
    __shared__ float shT[HH][4];
    __shared__ float sg[4][G4];
    __shared__ int ridx[4][TT];
    int so = g >> 7, d = g & 127;
    float creg = 0.f;
    shT[d][so] = 0.f;
    for (int i = g; i < WCACHE * G4; i += 512) sW[i] = WT[i];
    for (int i = g; i < 4 * TT; i += 512) {
        int s = i >> 5, t = i & 31;
        int seq = s0 + s; if (seq >= NSEQ) seq = NSEQ - 1;
        ridx[s][t] = d_rowIdx[seq * TT + t];
    }
    __syncthreads();
    int nv = NSEQ - s0; if (nv > 4) nv = 4;
    const float* preBase = d_preAll + dir * G4 + g;
    for (int step = 0; step < TT; step++) {
        int t = dir ? (TT - 1 - step) : step;
        float p0 = preBase[(size_t)ridx[0][t] * GCAT] + bias;
        float p1 = preBase[(size_t)ridx[1][t] * GCAT] + bias;
        float p2 = preBase[(size_t)ridx[2][t] * GCAT] + bias;
        float p3 = preBase[(size_t)ridx[3][t] * GCAT] + bias;
        ull a01 = pack2(p0, p1);
        ull a23 = pack2(p2, p3);
#pragma unroll 8
        for (int j = 0; j < WCACHE; j++) {
            float wv = sW[j * G4 + g];
            ulonglong2 h2 = *(const ulonglong2*)&shT[j][0];
            ull wd = pack2(wv, wv);
            fma2(a01, wd, h2.x);
            fma2(a23, wd, h2.y);
        }
#pragma unroll 8
        for (int j = WCACHE; j < HH; j++) {
            float wv = __ldg(WT + (size_t)j * G4 + g);
            ulonglong2 h2 = *(const ulonglong2*)&shT[j][0];
            ull wd = pack2(wv, wv);
            fma2(a01, wd, h2.x);
            fma2(a23, wd, h2.y);
        }
        float2 f01 = unpack2(a01);
        float2 f23 = unpack2(a23);
        sg[0][g] = f01.x; sg[1][g] = f01.y; sg[2][g] = f23.x; sg[3][g] = f23.y;
        __syncthreads();
        if (so < nv) {
            float iv = sg[so][d];
            float fv = sg[so][d + HH];
            float gv = sg[so][d + 2 * HH];
            float ov = sg[so][d + 3 * HH];
            float cn = sigm(fv) * creg + sigm(iv) * tanhf(gv);
            float hn = sigm(ov) * tanhf(cn);
            creg = cn;
            shT[d][so] = hn;
            d_Hcat[((size_t)(s0 + so) * TT + t) * HDIM + dir * HH + d] = hn;
        }
        __syncthreads();
    }
}

/* ------------------------------ BiDAF + score ------------------------------ */
__global__ void att_kernel(const float* __restrict__ wc, const float* __restrict__ bc,
                           const float* __restrict__ wq, const float* __restrict__ bq,
                           const float* __restrict__ wcq, const float* __restrict__ bcq,
                           const float* __restrict__ wz, const float* __restrict__ bz) {
    int b = blockIdx.x;
    int pair = blockIdx.y;
    int tid = threadIdx.x;
    int cseq = pair ? 192 : 128 + b;
    int qseq = pair ? 64 + b : b;
    const float* Cg = d_Hcat + (size_t)cseq * TT * HDIM;
    const float* Qg = d_Hcat + (size_t)qseq * TT * HDIM;
    __shared__ float CS[TT * HDIM];
    __shared__ float S[TT * TT];
    __shared__ float Aw[TT * TT];
    __shared__ float CD[TT], QD[TT], SMX[TT], BV[TT];
    __shared__ float Q2C[HDIM];
    __shared__ float RED[8];
    for (int i = tid; i < TT * HDIM; i += 256) CS[i] = Cg[i];
    __syncthreads();
    if (tid < TT) {
        float s = 0.f;
        const float* crow = CS + tid * HDIM;
        for (int d = 0; d < HDIM; d++) s += crow[d] * wc[d];
        CD[tid] = s;
    } else if (tid < 2 * TT) {
        int j = tid - TT;
        float s = 0.f;
        const float* qrow = Qg + (size_t)j * HDIM;
        for (int d = 0; d < HDIM; d++) s += qrow[d] * wq[d];
        QD[j] = s;
    }
    __syncthreads();
    float bsum = bc[0] + bq[0] + bcq[0];
#pragma unroll
    for (int r = 0; r < 4; r++) {
        int pi = tid * 4 + r;
        int i = pi >> 5, j = pi & 31;
        const float* crow = CS + i * HDIM;
        const float* qrow = Qg + (size_t)j * HDIM;
        float s = 0.f;
        for (int d = 0; d < HDIM; d++) s += crow[d] * qrow[d] * wcq[d];
        S[pi] = s + CD[i] + QD[j] + bsum;
    }
    __syncthreads();
    int lane = tid & 31, warp = tid >> 5;
    for (int i = warp; i < TT; i += 8) {
        float v = S[i * 32 + lane];
        float mx = v;
        for (int o = 16; o; o >>= 1) mx = fmaxf(mx, __shfl_xor_sync(0xffffffffu, mx, o));
        float e = expf(v - mx);
        float sm = e;
        for (int o = 16; o; o >>= 1) sm += __shfl_xor_sync(0xffffffffu, sm, o);
        Aw[i * 32 + lane] = e / sm;
        if (lane == 0) SMX[i] = mx;
    }
    __syncthreads();
    if (warp == 0) {
        float v = SMX[lane];
        float mx = v;
        for (int o = 16; o; o >>= 1) mx = fmaxf(mx, __shfl_xor_sync(0xffffffffu, mx, o));
        float e = expf(v - mx);
        float sm = e;
        for (int o = 16; o; o >>= 1) sm += __shfl_xor_sync(0xffffffffu, sm, o);
        BV[lane] = e / sm;
    }
    __syncthreads();
    {
        float s = 0.f;
        for (int i = 0; i < TT; i++) s += BV[i] * CS[i * HDIM + tid];
        Q2C[tid] = s;
    }
    __syncthreads();
    float bzv = bz[0];
    for (int i = 0; i < TT; i++) {
        int d = tid;
        float c2q = 0.f;
        for (int j = 0; j < TT; j++) c2q += Aw[i * 32 + j] * Qg[(size_t)j * HDIM + d];
        float cv = CS[i * HDIM + d];
        float term = cv * wz[d] + c2q * wz[HDIM + d] + cv * c2q * wz[2 * HDIM + d]
                   + cv * Q2C[d] * wz[3 * HDIM + d];
        for (int o = 16; o; o >>= 1) term += __shfl_xor_sync(0xffffffffu, term, o);
        if (lane == 0) RED[warp] = term;
        __syncthreads();
        if (tid == 0) {
            float tot = 0.f;
            for (int w2 = 0; w2 < 8; w2++) tot += RED[w2];
            d_p[(pair * MENT + b) * KCAND + i] = tot + bzv;
        }
        __syncthreads();
    }
}

__global__ void zero_kernel(float* __restrict__ out, int n) {
    int idx = blockIdx.x * blockDim.x + threadIdx.x;
    if (idx < n) out[idx] = 0.f;
}

__global__ void score_kernel(const int* __restrict__ cand,
                             const float* __restrict__ wp1, const float* __restrict__ bp1,
                             const float* __restrict__ wp2, const float* __restrict__ bp2,
                             float* __restrict__ out) {
    int b = blockIdx.x, i = threadIdx.x;
    float p1 = d_p[(0 * MENT + b) * KCAND + i];
    float p2 = d_p[(1 * MENT + b) * KCAND + i];
    float sc = wp1[0] * p1 + bp1[0] + wp2[0] * p2 + bp2[0];
    float mx = sc;
    for (int o = 16; o; o >>= 1) mx = fmaxf(mx, __shfl_xor_sync(0xffffffffu, mx, o));
    float e = expf(sc - mx);
    float es = e;
    for (int o = 16; o; o >>= 1) es += __shfl_xor_sync(0xffffffffu, es, o);
    float ssum = sc;
    for (int o = 16; o; o >>= 1) ssum += __shfl_xor_sync(0xffffffffu, ssum, o);
    int col = cand[b * KCAND + i];
    out[(size_t)b * N_ENT + col] = sc;
    out[(size_t)MENT * N_ENT + (size_t)b * N_ENT + col] = e / es;
    out[(size_t)2 * MENT * N_ENT + (size_t)b * N_ENT + col] = sc / ssum;
}

/* ------------------------------- launcher ---------------------------------- */
extern "C" void kernel_launch(void* const* d_in, const int* in_sizes, int n_in,
                              void* d_out, int out_size) {
    const int*   title  = (const int*)d_in[0];
    const int*   body   = (const int*)d_in[1];
    const int*   ctx    = (const int*)d_in[3];
    const int*   doc    = (const int*)d_in[4];
    const int*   cand   = (const int*)d_in[5];
    const float* emb    = (const float*)d_in[6];
    const float* conv_w = (const float*)d_in[7];
    const float* conv_b = (const float*)d_in[8];
    const float* Wih_f  = (const float*)d_in[9];
    const float* Whh_f  = (const float*)d_in[10];
    const float* bih_f  = (const float*)d_in[11];
    const float* bhh_f  = (const float*)d_in[12];
    const float* Wih_b  = (const float*)d_in[13];
    const float* Whh_b  = (const float*)d_in[14];
    const float* bih_b  = (const float*)d_in[15];
    const float* bhh_b  = (const float*)d_in[16];
    const float* wc  = (const float*)d_in[17];
    const float* bc  = (const float*)d_in[18];
    const float* wq  = (const float*)d_in[19];
    const float* bq  = (const float*)d_in[20];
    const float* wcq = (const float*)d_in[21];
    const float* bcq = (const float*)d_in[22];
    const float* wz  = (const float*)d_in[23];
    const float* bz  = (const float*)d_in[24];
    const float* wp1 = (const float*)d_in[25];
    const float* bp1 = (const float*)d_in[26];
    const float* wp2 = (const float*)d_in[27];
    const float* bp2 = (const float*)d_in[28];
    float* out = (float*)d_out;
    (void)in_sizes; (void)n_in; (void)out_size;

    void *pTh, *pPre;
    __nv_bfloat16 *pEH, *pEL, *pBH, *pBL, *pFH, *pFL, *pWH, *pWL;
    cudaGetSymbolAddress(&pTh, d_Th);
    cudaGetSymbolAddress(&pPre, d_preAll);
    cudaGetSymbolAddress((void**)&pEH, d_embH);
    cudaGetSymbolAddress((void**)&pEL, d_embL);
    cudaGetSymbolAddress((void**)&pBH, d_BmtH);
    cudaGetSymbolAddress((void**)&pBL, d_BmtL);
    cudaGetSymbolAddress((void**)&pFH, d_FH);
    cudaGetSymbolAddress((void**)&pFL, d_FL);
    cudaGetSymbolAddress((void**)&pWH, d_WcH);
    cudaGetSymbolAddress((void**)&pWL, d_WcL);

    static int attr_set = 0;
    if (!attr_set) {
        cudaFuncSetAttribute(lstm_kernel, cudaFuncAttributeMaxDynamicSharedMemorySize,
                             WCACHE * G4 * (int)sizeof(float));
        cudaFuncSetAttribute(mma_gemm, cudaFuncAttributeMaxDynamicSharedMemorySize,
                             GEMM_SMEM);
        attr_set = 1;
    }

    /* 1-3: prep (gemm1 deps first) */
    prep0_kernel<<<(N_ENT + 256) / 256, 256>>>();
    prep1_kernel<<<(PTOT + 255) / 256, 256>>>(emb, conv_w, Wih_f, Wih_b, Whh_f, Whh_b, cand);
    prep2_kernel<<<(N_ENT + 255) / 256, 256>>>();

    /* 4: token table T(fp16) = emb @ Bmat^T : [5120 x 2560], K=320 (profiled) */
    mma_gemm<<<dim3(WNC / 128, VOCABP / 128), 256, GEMM_SMEM>>>(
        pEH, pEL, pBH, pBL, pTh, KP1, WNC, KP1 / 32, 0, 1);

    /* 5: char-CNN features */
    conv_all<<<1 + N_ENT + MENT + N_ENT, 256>>>(title, body, ctx, doc, conv_b);

    /* 6-7: LSTM row index + zero output */
    prep3_kernel<<<(NSEQ * TT + 255) / 256, 256>>>(cand);
    {
        int n = 3 * MENT * N_ENT;
        zero_kernel<<<(n + 255) / 256, 256>>>(out, n);
    }

    /* 8: pre-activations = F @ Wih^T : [4224 x 1024], K=512, fp32 out */
    mma_gemm<<<dim3(GCAT / 128, NFEATP / 128), 256, GEMM_SMEM>>>(
        pFH, pFL, pWH, pWL, pPre, CCS, GCAT, CCS / 32, 1, 0);

    /* 9: recurrence */
    lstm_kernel<<<dim3((NSEQ + 3) / 4, 2), 512, WCACHE * G4 * sizeof(float)>>>(
        bih_f, bhh_f, bih_b, bhh_b);

    /* 10: BiDAF attention + projection */
    att_kernel<<<dim3(MENT, 2), 256>>>(wc, bc, wq, bq, wcq, bcq, wz, bz);

    /* 11: score, softmax, sum-normalize, scatter */
    score_kernel<<<MENT, KCAND>>>(cand, wp1, bp1, wp2, bp2, out);
}